// round 13
// baseline (speedup 1.0000x reference)
#include <cuda_runtime.h>
#include <cuda_bf16.h>
#include <cstdint>

// Problem constants
#define BB   2
#define SS   1024
#define DD   2048
#define QH   32
#define KH   8
#define HD   64
#define KVD  (KH*HD)        // 512
#define MTOT (BB*SS)        // 2048

typedef __nv_bfloat16 bf16;
typedef __nv_bfloat162 bf162;

// ---------------- scratch (device globals; alignas(16) for cp.async) -------
__device__ alignas(16) bf16 g_qh[MTOT * DD],  g_ql[MTOT * DD];
__device__ alignas(16) bf16 g_kvh[MTOT * DD], g_kvl[MTOT * DD];
__device__ alignas(16) bf16 g_Wqt_h[DD * DD],  g_Wqt_l[DD * DD];     // [n][k]
__device__ alignas(16) bf16 g_Wkt_h[KVD * DD], g_Wkt_l[KVD * DD];
__device__ alignas(16) bf16 g_Wvt_h[KVD * DD], g_Wvt_l[KVD * DD];
__device__ alignas(16) bf16 g_Wot_h[DD * DD],  g_Wot_l[DD * DD];
__device__ alignas(16) bf16 g_Qsh[MTOT * DD],  g_Qsl[MTOT * DD];
__device__ alignas(16) bf16 g_Ksh[MTOT * KVD], g_Ksl[MTOT * KVD];
__device__ alignas(16) bf16 g_Vth[BB * KVD * SS], g_Vtl[BB * KVD * SS]; // V^T
__device__ alignas(16) bf16 g_Aoh[MTOT * DD], g_Aol[MTOT * DD];

__device__ __forceinline__ void split_bf16(float v, bf16& h, bf16& l) {
    h = __float2bfloat16_rn(v);
    l = __float2bfloat16_rn(v - __bfloat162float(h));
}
__device__ __forceinline__ uint32_t pack2(bf16 a, bf16 b) {
    bf162 t = __halves2bfloat162(a, b);
    return *(uint32_t*)&t;
}
// packed split of two floats: hp = pack2(bf(a), bf(b)), lp = pack2(residuals)
__device__ __forceinline__ void split2(float a, float b, uint32_t& hp, uint32_t& lp) {
    asm("cvt.rn.bf16x2.f32 %0, %1, %2;" : "=r"(hp) : "f"(b), "f"(a));
    float ha = __uint_as_float(hp << 16);
    float hb = __uint_as_float(hp & 0xFFFF0000u);
    float la = a - ha, lb = b - hb;
    asm("cvt.rn.bf16x2.f32 %0, %1, %2;" : "=r"(lp) : "f"(lb), "f"(la));
}
__device__ __forceinline__ void cpa16(void* dst, const void* src) {
    uint32_t d = (uint32_t)__cvta_generic_to_shared(dst);
    asm volatile("cp.async.ca.shared.global [%0], [%1], 16;" :: "r"(d), "l"(src));
}
__device__ __forceinline__ void ldmx4(uint32_t* r, const void* p) {
    uint32_t addr = (uint32_t)__cvta_generic_to_shared(p);
    asm volatile("ldmatrix.sync.aligned.m8n8.x4.shared.b16 {%0,%1,%2,%3}, [%4];"
                 : "=r"(r[0]), "=r"(r[1]), "=r"(r[2]), "=r"(r[3]) : "r"(addr));
}
__device__ __forceinline__ void mma16816(float* c, const uint32_t* a, const uint32_t* b) {
    asm volatile("mma.sync.aligned.m16n8k16.row.col.f32.bf16.bf16.f32 "
                 "{%0,%1,%2,%3}, {%4,%5,%6,%7}, {%8,%9}, {%0,%1,%2,%3};"
                 : "+f"(c[0]), "+f"(c[1]), "+f"(c[2]), "+f"(c[3])
                 : "r"(a[0]), "r"(a[1]), "r"(a[2]), "r"(a[3]),
                   "r"(b[0]), "r"(b[1]));
}

// ---------------- convert kernels (fused) ----------------
__global__ void k_split2in(const float* __restrict__ a, bf16* __restrict__ ah, bf16* __restrict__ al,
                           const float* __restrict__ b, bf16* __restrict__ bh, bf16* __restrict__ bl,
                           int n)
{
    const float* in = blockIdx.z ? b : a;
    bf16* hi = blockIdx.z ? bh : ah;
    bf16* lo = blockIdx.z ? bl : al;
    int i = (blockIdx.x * blockDim.x + threadIdx.x) * 4;
    if (i >= n) return;
    float4 v = *(const float4*)&in[i];
    uint32_t h0, l0, h1, l1;
    split2(v.x, v.y, h0, l0);
    split2(v.z, v.w, h1, l1);
    *(uint32_t*)&hi[i]     = h0; *(uint32_t*)&hi[i + 2] = h1;
    *(uint32_t*)&lo[i]     = l0; *(uint32_t*)&lo[i + 2] = l1;
}

// transpose + split, 4 weights in one launch (z selects). in fp32 [DD][C] -> [C][DD]
__global__ void k_tsplit4(const float* __restrict__ i0, bf16* __restrict__ h0, bf16* __restrict__ l0,
                          const float* __restrict__ i1, bf16* __restrict__ h1, bf16* __restrict__ l1,
                          const float* __restrict__ i2, bf16* __restrict__ h2, bf16* __restrict__ l2,
                          const float* __restrict__ i3, bf16* __restrict__ h3, bf16* __restrict__ l3)
{
    const int z = blockIdx.z;
    const float* in = (z == 0) ? i0 : (z == 1) ? i1 : (z == 2) ? i2 : i3;
    bf16* hi = (z == 0) ? h0 : (z == 1) ? h1 : (z == 2) ? h2 : h3;
    bf16* lo = (z == 0) ? l0 : (z == 1) ? l1 : (z == 2) ? l2 : l3;
    const int C = (z < 2) ? DD : KVD;
    const int R = DD;
    int r0 = blockIdx.y * 32, c0 = blockIdx.x * 32;
    if (c0 >= C) return;
    __shared__ float t[32][33];
#pragma unroll
    for (int i = 0; i < 4; i++) {
        int r = r0 + threadIdx.y + i * 8;
        t[threadIdx.y + i * 8][threadIdx.x] = in[(size_t)r * C + c0 + threadIdx.x];
    }
    __syncthreads();
#pragma unroll
    for (int i = 0; i < 4; i++) {
        int c = c0 + threadIdx.y + i * 8;
        float v = t[threadIdx.x][threadIdx.y + i * 8];
        bf16 h, l; split_bf16(v, h, l);
        hi[(size_t)c * R + r0 + threadIdx.x] = h;
        lo[(size_t)c * R + r0 + threadIdx.x] = l;
    }
}

// ============================================================================
// Tensor-core GEMM on pre-split bf16, templated on N-tile width TBN.
// Epilogue modes: 0 fp32 C, 1 split bf16 (with scale), 2 split bf16 V-T
// ============================================================================
#define BM 128
#define BK 32
#define KSTR 40
#define A_TBF (BM * KSTR)

template<int TBN>
__global__ __launch_bounds__(256, 2)
void gemm_tc(const bf16* __restrict__ Ah, const bf16* __restrict__ Al,
             const bf16* __restrict__ B0h, const bf16* __restrict__ B0l,
             const float* __restrict__ b0, float* __restrict__ C0,
             bf16* __restrict__ C0h, bf16* __restrict__ C0l, int mode0,
             const bf16* __restrict__ B1h, const bf16* __restrict__ B1l,
             const float* __restrict__ b1, float* __restrict__ C1,
             bf16* __restrict__ C1h, bf16* __restrict__ C1l, int mode1,
             float scale, int M, int N, int K)
{
    constexpr int B_TBF = TBN * KSTR;
    constexpr int STG   = 2 * A_TBF + 2 * B_TBF;   // Ah,Al,Bh,Bl
    constexpr int NJ    = TBN / 32;                // n8 frags per warp
    constexpr int WNC   = TBN / 4;                 // cols per warp

    const bf16* Bh   = blockIdx.z ? B1h : B0h;
    const bf16* Bl   = blockIdx.z ? B1l : B0l;
    const float* bias = blockIdx.z ? b1 : b0;
    float* C   = blockIdx.z ? C1 : C0;
    bf16*  Ch  = blockIdx.z ? C1h : C0h;
    bf16*  Cl  = blockIdx.z ? C1l : C0l;
    const int mode = blockIdx.z ? mode1 : mode0;

    extern __shared__ bf16 smem[];

    const int tid  = threadIdx.x;
    const int lane = tid & 31;
    const int wid  = tid >> 5;
    const int wm   = wid & 1;
    const int wn   = wid >> 1;
    const int row0 = blockIdx.y * BM;
    const int col0 = blockIdx.x * TBN;

    float acc[4][NJ][4];
#pragma unroll
    for (int i = 0; i < 4; i++)
#pragma unroll
        for (int j = 0; j < NJ; j++)
#pragma unroll
            for (int k = 0; k < 4; k++) acc[i][j][k] = 0.f;

    const int a_r = lane & 15;
    const int a_k = (lane >> 4) << 3;
    const int b_r = (lane & 7) | ((lane & 16) >> 1);
    const int b_k = lane & 8;

    const int nt = K / BK;

    auto stage_tiles = [&](bf16* base, int kt) {
        bf16* pAh = base;                 bf16* pAl = base + A_TBF;
        bf16* pBh = base + 2 * A_TBF;     bf16* pBl = base + 2 * A_TBF + B_TBF;
#pragma unroll
        for (int p = 0; p < 2; p++) {     // A: 512 chunks
            int c   = tid + p * 256;
            int r   = c >> 2;
            int off = (c & 3) * 8;
            const size_t ga = (size_t)(row0 + r) * K + kt + off;
            const int so = r * KSTR + off;
            cpa16(pAh + so, Ah + ga);
            cpa16(pAl + so, Al + ga);
        }
#pragma unroll
        for (int p = 0; p < TBN / 64; p++) {   // B: TBN*4 chunks
            int c   = tid + p * 256;
            int r   = c >> 2;
            int off = (c & 3) * 8;
            const size_t gb = (size_t)(col0 + r) * K + kt + off;
            const int so = r * KSTR + off;
            cpa16(pBh + so, Bh + gb);
            cpa16(pBl + so, Bl + gb);
        }
    };

    stage_tiles(smem, 0);
    asm volatile("cp.async.commit_group;");

    for (int t = 0; t < nt; t++) {
        if (t + 1 < nt)
            stage_tiles(smem + ((t + 1) & 1) * STG, (t + 1) * BK);
        asm volatile("cp.async.commit_group;");
        asm volatile("cp.async.wait_group 1;");
        __syncthreads();

        bf16* base = smem + (t & 1) * STG;
        bf16* pAh = base;             bf16* pAl = base + A_TBF;
        bf16* pBh = base + 2*A_TBF;   bf16* pBl = base + 2*A_TBF + B_TBF;

#pragma unroll
        for (int kk = 0; kk < BK; kk += 16) {
            uint32_t af[4][4], bh[(NJ + 1) / 2][4], bl[(NJ + 1) / 2][4];
#pragma unroll
            for (int i = 0; i < 4; i++)
                ldmx4(af[i], pAh + (wm * 64 + i * 16 + a_r) * KSTR + kk + a_k);
#pragma unroll
            for (int j = 0; j < NJ / 2; j++)
                ldmx4(bh[j], pBh + (wn * WNC + j * 16 + b_r) * KSTR + kk + b_k);
#pragma unroll
            for (int j = 0; j < NJ / 2; j++)
                ldmx4(bl[j], pBl + (wn * WNC + j * 16 + b_r) * KSTR + kk + b_k);

#pragma unroll
            for (int i = 0; i < 4; i++)
#pragma unroll
                for (int j = 0; j < NJ; j++)
                    mma16816(acc[i][j], af[i], &bh[j >> 1][(j & 1) * 2]);
#pragma unroll
            for (int i = 0; i < 4; i++)
#pragma unroll
                for (int j = 0; j < NJ; j++)
                    mma16816(acc[i][j], af[i], &bl[j >> 1][(j & 1) * 2]);
#pragma unroll
            for (int i = 0; i < 4; i++)
                ldmx4(af[i], pAl + (wm * 64 + i * 16 + a_r) * KSTR + kk + a_k);
#pragma unroll
            for (int i = 0; i < 4; i++)
#pragma unroll
                for (int j = 0; j < NJ; j++)
                    mma16816(acc[i][j], af[i], &bh[j >> 1][(j & 1) * 2]);
        }
        __syncthreads();
    }

    // epilogue
#pragma unroll
    for (int i = 0; i < 4; i++) {
        int gr = row0 + wm * 64 + i * 16 + (lane >> 2);
#pragma unroll
        for (int j = 0; j < NJ; j++) {
            int gc = col0 + wn * WNC + j * 8 + (lane & 3) * 2;
            float bx = bias[gc], by = bias[gc + 1];
            float v0 = (acc[i][j][0] + bx) * scale, v1 = (acc[i][j][1] + by) * scale;
            float v2 = (acc[i][j][2] + bx) * scale, v3 = (acc[i][j][3] + by) * scale;
            if (mode == 0) {
                *(float2*)&C[(size_t)gr * N + gc]       = make_float2(v0, v1);
                *(float2*)&C[(size_t)(gr + 8) * N + gc] = make_float2(v2, v3);
            } else if (mode == 1) {
                uint32_t hp0, lp0, hp1, lp1;
                split2(v0, v1, hp0, lp0);
                split2(v2, v3, hp1, lp1);
                *(uint32_t*)&Ch[(size_t)gr * N + gc]       = hp0;
                *(uint32_t*)&Cl[(size_t)gr * N + gc]       = lp0;
                *(uint32_t*)&Ch[(size_t)(gr + 8) * N + gc] = hp1;
                *(uint32_t*)&Cl[(size_t)(gr + 8) * N + gc] = lp1;
            } else {
                int b0i = gr >> 10, s0 = gr & 1023;
                int b1i = (gr + 8) >> 10, s1 = (gr + 8) & 1023;
                bf16 h, l;
                size_t i00 = ((size_t)b0i * KVD + gc) * SS + s0;
                size_t i01 = ((size_t)b0i * KVD + gc + 1) * SS + s0;
                size_t i10 = ((size_t)b1i * KVD + gc) * SS + s1;
                size_t i11 = ((size_t)b1i * KVD + gc + 1) * SS + s1;
                split_bf16(v0, h, l); Ch[i00] = h; Cl[i00] = l;
                split_bf16(v1, h, l); Ch[i01] = h; Cl[i01] = l;
                split_bf16(v2, h, l); Ch[i10] = h; Cl[i10] = l;
                split_bf16(v3, h, l); Ch[i11] = h; Cl[i11] = l;
            }
        }
    }
}

#define GEMM_SMEM_128 (2 * (2 * A_TBF + 2 * 128 * KSTR) * 2)
#define GEMM_SMEM_64  (2 * (2 * A_TBF + 2 * 64  * KSTR) * 2)

// ============================================================================
// Tensor-core causal GQA flash attention, double-buffered K/V pipeline.
// Q pre-scaled by 0.125 at projection; mask pass only on diagonal tiles.
// ============================================================================
#define QSTR 72
#define KVSTG (4 * 64 * QSTR)
#define ATTN_SMEM (2 * KVSTG * 2)

__global__ __launch_bounds__(256)
void attn_mma(const bf16* __restrict__ Qh, const bf16* __restrict__ Ql,
              const bf16* __restrict__ Kh, const bf16* __restrict__ Kl,
              const bf16* __restrict__ Vth, const bf16* __restrict__ Vtl,
              bf16* __restrict__ Aoh, bf16* __restrict__ Aol)
{
    extern __shared__ bf16 sm[];
    bf16* sQh = sm;
    bf16* sQl = sm + 128 * QSTR;

    const int tid = threadIdx.x, lane = tid & 31, wid = tid >> 5;
    const int y  = blockIdx.x;
    const int bh = blockIdx.y;
    const int b  = bh >> 5, h = bh & 31, kh = h >> 2;
    const int qtok0 = b * SS + y * 128;

    const int a_r = lane & 15;
    const int a_k = (lane >> 4) << 3;
    const int b_r = (lane & 7) | ((lane & 16) >> 1);
    const int b_k = lane & 8;

#pragma unroll
    for (int p = 0; p < 4; p++) {
        int c = tid + p * 256;
        int r = c >> 3, off = (c & 7) * 8;
        const size_t g = (size_t)(qtok0 + r) * DD + h * HD + off;
        cpa16(sQh + r * QSTR + off, Qh + g);
        cpa16(sQl + r * QSTR + off, Ql + g);
    }
    asm volatile("cp.async.commit_group;");
    asm volatile("cp.async.wait_group 0;");
    __syncthreads();

    uint32_t qah[4][4], qal[4][4];
#pragma unroll
    for (int kk = 0; kk < 4; kk++) {
        ldmx4(qah[kk], sQh + (wid * 16 + a_r) * QSTR + kk * 16 + a_k);
        ldmx4(qal[kk], sQl + (wid * 16 + a_r) * QSTR + kk * 16 + a_k);
    }
    __syncthreads();

    float oacc[8][4];
#pragma unroll
    for (int f = 0; f < 8; f++)
#pragma unroll
        for (int e = 0; e < 4; e++) oacc[f][e] = 0.f;
    float mA = -1e30f, mB = -1e30f, lA = 0.f, lB = 0.f;

    const int qrowA = y * 128 + wid * 16 + (lane >> 2);
    const int jend = 2 * y + 1;

    auto stage_kv = [&](int s, int j) {
        bf16* base = sm + s * KVSTG;
        bf16* pKh = base;
        bf16* pKl = base + 64 * QSTR;
        bf16* pVh = base + 128 * QSTR;
        bf16* pVl = base + 192 * QSTR;
        const int ktok0 = b * SS + j * 64;
#pragma unroll
        for (int p = 0; p < 2; p++) {
            int c = tid + p * 256;
            int r = c >> 3, off = (c & 7) * 8;
            const size_t gk = (size_t)(ktok0 + r) * KVD + kh * HD + off;
            cpa16(pKh + r * QSTR + off, Kh + gk);
            cpa16(pKl + r * QSTR + off, Kl + gk);
            const size_t gv = ((size_t)b * KVD + kh * HD + r) * SS + j * 64 + off;
            cpa16(pVh + r * QSTR + off, Vth + gv);
            cpa16(pVl + r * QSTR + off, Vtl + gv);
        }
    };

    stage_kv(0, 0);
    asm volatile("cp.async.commit_group;");

    for (int j = 0; j <= jend; j++) {
        if (j + 1 <= jend)
            stage_kv((j + 1) & 1, j + 1);
        asm volatile("cp.async.commit_group;");
        asm volatile("cp.async.wait_group 1;");
        __syncthreads();

        bf16* base = sm + (j & 1) * KVSTG;
        bf16* sKh = base;
        bf16* sKl = base + 64 * QSTR;
        bf16* sVh = base + 128 * QSTR;
        bf16* sVl = base + 192 * QSTR;

        if (j * 64 <= y * 128 + wid * 16 + 15) {
            // ---- S = Q K^T (Q pre-scaled), 3-term split ----
            float sacc[8][4];
#pragma unroll
            for (int f = 0; f < 8; f++)
#pragma unroll
                for (int e = 0; e < 4; e++) sacc[f][e] = 0.f;

            uint32_t kb[4][4];
#pragma unroll
            for (int kk = 0; kk < 4; kk++) {
#pragma unroll
                for (int nb = 0; nb < 4; nb++)
                    ldmx4(kb[nb], sKh + (nb * 16 + b_r) * QSTR + kk * 16 + b_k);
#pragma unroll
                for (int f = 0; f < 8; f++)
                    mma16816(sacc[f], qah[kk], &kb[f >> 1][(f & 1) * 2]);
#pragma unroll
                for (int f = 0; f < 8; f++)
                    mma16816(sacc[f], qal[kk], &kb[f >> 1][(f & 1) * 2]);
#pragma unroll
                for (int nb = 0; nb < 4; nb++)
                    ldmx4(kb[nb], sKl + (nb * 16 + b_r) * QSTR + kk * 16 + b_k);
#pragma unroll
                for (int f = 0; f < 8; f++)
                    mma16816(sacc[f], qah[kk], &kb[f >> 1][(f & 1) * 2]);
            }

            // ---- causal mask: only diagonal supertiles need it ----
            if (j >= 2 * y) {
#pragma unroll
                for (int f = 0; f < 8; f++)
#pragma unroll
                    for (int e = 0; e < 4; e++) {
                        int kg = j * 64 + f * 8 + (lane & 3) * 2 + (e & 1);
                        int qg = qrowA + (e >> 1) * 8;
                        if (kg > qg) sacc[f][e] = -1e30f;
                    }
            }

            // ---- online softmax (rows A: e0/e1, rows B: e2/e3) ----
            float tmA = -1e30f, tmB = -1e30f;
#pragma unroll
            for (int f = 0; f < 8; f++) {
                tmA = fmaxf(tmA, fmaxf(sacc[f][0], sacc[f][1]));
                tmB = fmaxf(tmB, fmaxf(sacc[f][2], sacc[f][3]));
            }
            tmA = fmaxf(tmA, __shfl_xor_sync(0xffffffffu, tmA, 1));
            tmA = fmaxf(tmA, __shfl_xor_sync(0xffffffffu, tmA, 2));
            tmB = fmaxf(tmB, __shfl_xor_sync(0xffffffffu, tmB, 1));
            tmB = fmaxf(tmB, __shfl_xor_sync(0xffffffffu, tmB, 2));
            float mnA = fmaxf(mA, tmA), mnB = fmaxf(mB, tmB);
            float alA = __expf(mA - mnA), alB = __expf(mB - mnB);
            mA = mnA; mB = mnB;

            float suA = 0.f, suB = 0.f;
#pragma unroll
            for (int f = 0; f < 8; f++) {
                float p0 = __expf(sacc[f][0] - mA);
                float p1 = __expf(sacc[f][1] - mA);
                float p2 = __expf(sacc[f][2] - mB);
                float p3 = __expf(sacc[f][3] - mB);
                suA += p0 + p1; suB += p2 + p3;
                sacc[f][0] = p0; sacc[f][1] = p1; sacc[f][2] = p2; sacc[f][3] = p3;
            }
            suA += __shfl_xor_sync(0xffffffffu, suA, 1);
            suA += __shfl_xor_sync(0xffffffffu, suA, 2);
            suB += __shfl_xor_sync(0xffffffffu, suB, 1);
            suB += __shfl_xor_sync(0xffffffffu, suB, 2);
            lA = lA * alA + suA; lB = lB * alB + suB;

#pragma unroll
            for (int f = 0; f < 8; f++) {
                oacc[f][0] *= alA; oacc[f][1] *= alA;
                oacc[f][2] *= alB; oacc[f][3] *= alB;
            }

            // ---- O += P V (per kc-chunk: packed split of P, MMA w/ Vt) ----
            uint32_t vb[4][4];
#pragma unroll
            for (int c = 0; c < 4; c++) {
                const int f0 = 2 * c, f1 = 2 * c + 1;
                uint32_t pah[4], pal[4];
                split2(sacc[f0][0], sacc[f0][1], pah[0], pal[0]);
                split2(sacc[f0][2], sacc[f0][3], pah[1], pal[1]);
                split2(sacc[f1][0], sacc[f1][1], pah[2], pal[2]);
                split2(sacc[f1][2], sacc[f1][3], pah[3], pal[3]);
#pragma unroll
                for (int nb = 0; nb < 4; nb++)
                    ldmx4(vb[nb], sVh + (nb * 16 + b_r) * QSTR + c * 16 + b_k);
#pragma unroll
                for (int f = 0; f < 8; f++)
                    mma16816(oacc[f], pah, &vb[f >> 1][(f & 1) * 2]);
#pragma unroll
                for (int f = 0; f < 8; f++)
                    mma16816(oacc[f], pal, &vb[f >> 1][(f & 1) * 2]);
#pragma unroll
                for (int nb = 0; nb < 4; nb++)
                    ldmx4(vb[nb], sVl + (nb * 16 + b_r) * QSTR + c * 16 + b_k);
#pragma unroll
                for (int f = 0; f < 8; f++)
                    mma16816(oacc[f], pah, &vb[f >> 1][(f & 1) * 2]);
            }
        }
        __syncthreads();
    }

    // ---- normalize + packed split-write O ----
    const float ivA = 1.f / lA, ivB = 1.f / lB;
    const int tokA = qtok0 + wid * 16 + (lane >> 2);
#pragma unroll
    for (int f = 0; f < 8; f++) {
        int col = h * HD + f * 8 + (lane & 3) * 2;
        uint32_t hpA, lpA, hpB, lpB;
        split2(oacc[f][0] * ivA, oacc[f][1] * ivA, hpA, lpA);
        split2(oacc[f][2] * ivB, oacc[f][3] * ivB, hpB, lpB);
        *(uint32_t*)&Aoh[(size_t)tokA * DD + col]       = hpA;
        *(uint32_t*)&Aol[(size_t)tokA * DD + col]       = lpA;
        *(uint32_t*)&Aoh[(size_t)(tokA + 8) * DD + col] = hpB;
        *(uint32_t*)&Aol[(size_t)(tokA + 8) * DD + col] = lpB;
    }
}

// ---------------- launcher ----------------
extern "C" void kernel_launch(void* const* d_in, const int* in_sizes, int n_in,
                              void* d_out, int out_size)
{
    const float* q  = (const float*)d_in[0];
    const float* kv = (const float*)d_in[1];
    // d_in[2] = mask (causal, static) -- unused
    const float* Wq = (const float*)d_in[3];
    const float* bq = (const float*)d_in[4];
    const float* Wk = (const float*)d_in[5];
    const float* bk = (const float*)d_in[6];
    const float* Wv = (const float*)d_in[7];
    const float* bv = (const float*)d_in[8];
    const float* Wo = (const float*)d_in[9];
    const float* bo = (const float*)d_in[10];
    float* out = (float*)d_out;

    bf16 *qh, *ql, *kvh, *kvl, *Wqth, *Wqtl, *Wkth, *Wktl, *Wvth_, *Wvtl_, *Woth, *Wotl;
    bf16 *Qsh, *Qsl, *Ksh, *Ksl, *Vth, *Vtl, *Aoh, *Aol;
    cudaGetSymbolAddress((void**)&qh,  g_qh);   cudaGetSymbolAddress((void**)&ql,  g_ql);
    cudaGetSymbolAddress((void**)&kvh, g_kvh);  cudaGetSymbolAddress((void**)&kvl, g_kvl);
    cudaGetSymbolAddress((void**)&Wqth, g_Wqt_h); cudaGetSymbolAddress((void**)&Wqtl, g_Wqt_l);
    cudaGetSymbolAddress((void**)&Wkth, g_Wkt_h); cudaGetSymbolAddress((void**)&Wktl, g_Wkt_l);
    cudaGetSymbolAddress((void**)&Wvth_, g_Wvt_h); cudaGetSymbolAddress((void**)&Wvtl_, g_Wvt_l);
    cudaGetSymbolAddress((void**)&Woth, g_Wot_h); cudaGetSymbolAddress((void**)&Wotl, g_Wot_l);
    cudaGetSymbolAddress((void**)&Qsh, g_Qsh);  cudaGetSymbolAddress((void**)&Qsl, g_Qsl);
    cudaGetSymbolAddress((void**)&Ksh, g_Ksh);  cudaGetSymbolAddress((void**)&Ksl, g_Ksl);
    cudaGetSymbolAddress((void**)&Vth, g_Vth);  cudaGetSymbolAddress((void**)&Vtl, g_Vtl);
    cudaGetSymbolAddress((void**)&Aoh, g_Aoh);  cudaGetSymbolAddress((void**)&Aol, g_Aol);

    cudaFuncSetAttribute(gemm_tc<128>,
                         cudaFuncAttributeMaxDynamicSharedMemorySize, GEMM_SMEM_128);
    cudaFuncSetAttribute(gemm_tc<64>,
                         cudaFuncAttributeMaxDynamicSharedMemorySize, GEMM_SMEM_64);
    cudaFuncSetAttribute(attn_mma,
                         cudaFuncAttributeMaxDynamicSharedMemorySize, ATTN_SMEM);

    // ---- converts (2 fused launches) ----
    k_split2in<<<dim3(MTOT * DD / 4 / 256, 1, 2), 256>>>(
        q, qh, ql, kv, kvh, kvl, MTOT * DD);
    k_tsplit4<<<dim3(DD / 32, DD / 32, 4), dim3(32, 8)>>>(
        Wq, Wqth, Wqtl, Wo, Woth, Wotl, Wk, Wkth, Wktl, Wv, Wvth_, Wvtl_);

    // ---- Q projection -> split bf16, pre-scaled by 1/sqrt(HD)=0.125 ----
    gemm_tc<128><<<dim3(DD / 128, MTOT / BM, 1), 256, GEMM_SMEM_128>>>(
        qh, ql, Wqth, Wqtl, bq, nullptr, Qsh, Qsl, 1,
        Wqth, Wqtl, bq, nullptr, Qsh, Qsl, 1, 0.125f, MTOT, DD, DD);

    // ---- K (split natural) and V (split transposed): BN=64 -> 256 CTAs ----
    gemm_tc<64><<<dim3(KVD / 64, MTOT / BM, 2), 256, GEMM_SMEM_64>>>(
        kvh, kvl, Wkth, Wktl, bk, nullptr, Ksh, Ksl, 1,
        Wvth_, Wvtl_, bv, nullptr, Vth, Vtl, 2, 1.0f, MTOT, KVD, DD);

    // ---- tensor-core attention -> Ao split ----
    attn_mma<<<dim3(SS / 128, BB * QH), 256, ATTN_SMEM>>>(
        Qsh, Qsl, Ksh, Ksl, Vth, Vtl, Aoh, Aol);

    // ---- output projection (fp32 out) ----
    gemm_tc<128><<<dim3(DD / 128, MTOT / BM, 1), 256, GEMM_SMEM_128>>>(
        Aoh, Aol, Woth, Wotl, bo, out, nullptr, nullptr, 0,
        Woth, Wotl, bo, out, nullptr, nullptr, 0, 1.0f, MTOT, DD, DD);
}

// round 14
// speedup vs baseline: 1.0386x; 1.0386x over previous
#include <cuda_runtime.h>
#include <cuda_bf16.h>
#include <cstdint>

// Problem constants
#define BB   2
#define SS   1024
#define DD   2048
#define QH   32
#define KH   8
#define HD   64
#define KVD  (KH*HD)        // 512
#define MTOT (BB*SS)        // 2048

typedef __nv_bfloat16 bf16;
typedef __nv_bfloat162 bf162;

// ---------------- scratch (device globals; alignas(16) for cp.async) -------
__device__ alignas(16) bf16 g_qh[MTOT * DD],  g_ql[MTOT * DD];
__device__ alignas(16) bf16 g_kvh[MTOT * DD], g_kvl[MTOT * DD];
__device__ alignas(16) bf16 g_Wqt_h[DD * DD],  g_Wqt_l[DD * DD];     // [n][k]
__device__ alignas(16) bf16 g_Wkt_h[KVD * DD], g_Wkt_l[KVD * DD];
__device__ alignas(16) bf16 g_Wvt_h[KVD * DD], g_Wvt_l[KVD * DD];
__device__ alignas(16) bf16 g_Wot_h[DD * DD],  g_Wot_l[DD * DD];
__device__ alignas(16) bf16 g_Qsh[MTOT * DD],  g_Qsl[MTOT * DD];
__device__ alignas(16) bf16 g_Ksh[MTOT * KVD], g_Ksl[MTOT * KVD];
__device__ alignas(16) bf16 g_Vth[BB * KVD * SS], g_Vtl[BB * KVD * SS]; // V^T
__device__ alignas(16) bf16 g_Aoh[MTOT * DD], g_Aol[MTOT * DD];

__device__ __forceinline__ void split_bf16(float v, bf16& h, bf16& l) {
    h = __float2bfloat16_rn(v);
    l = __float2bfloat16_rn(v - __bfloat162float(h));
}
__device__ __forceinline__ uint32_t pack2(bf16 a, bf16 b) {
    bf162 t = __halves2bfloat162(a, b);
    return *(uint32_t*)&t;
}
// packed split of two floats: hp = pack2(bf(a), bf(b)), lp = pack2(residuals)
__device__ __forceinline__ void split2(float a, float b, uint32_t& hp, uint32_t& lp) {
    asm("cvt.rn.bf16x2.f32 %0, %1, %2;" : "=r"(hp) : "f"(b), "f"(a));
    float ha = __uint_as_float(hp << 16);
    float hb = __uint_as_float(hp & 0xFFFF0000u);
    float la = a - ha, lb = b - hb;
    asm("cvt.rn.bf16x2.f32 %0, %1, %2;" : "=r"(lp) : "f"(lb), "f"(la));
}
__device__ __forceinline__ void cpa16(void* dst, const void* src) {
    uint32_t d = (uint32_t)__cvta_generic_to_shared(dst);
    asm volatile("cp.async.ca.shared.global [%0], [%1], 16;" :: "r"(d), "l"(src));
}
__device__ __forceinline__ void ldmx4(uint32_t* r, const void* p) {
    uint32_t addr = (uint32_t)__cvta_generic_to_shared(p);
    asm volatile("ldmatrix.sync.aligned.m8n8.x4.shared.b16 {%0,%1,%2,%3}, [%4];"
                 : "=r"(r[0]), "=r"(r[1]), "=r"(r[2]), "=r"(r[3]) : "r"(addr));
}
__device__ __forceinline__ void mma16816(float* c, const uint32_t* a, const uint32_t* b) {
    asm volatile("mma.sync.aligned.m16n8k16.row.col.f32.bf16.bf16.f32 "
                 "{%0,%1,%2,%3}, {%4,%5,%6,%7}, {%8,%9}, {%0,%1,%2,%3};"
                 : "+f"(c[0]), "+f"(c[1]), "+f"(c[2]), "+f"(c[3])
                 : "r"(a[0]), "r"(a[1]), "r"(a[2]), "r"(a[3]),
                   "r"(b[0]), "r"(b[1]));
}

// ---------------- convert kernels (fused) ----------------
__global__ void k_split2in(const float* __restrict__ a, bf16* __restrict__ ah, bf16* __restrict__ al,
                           const float* __restrict__ b, bf16* __restrict__ bh, bf16* __restrict__ bl,
                           int n)
{
    const float* in = blockIdx.z ? b : a;
    bf16* hi = blockIdx.z ? bh : ah;
    bf16* lo = blockIdx.z ? bl : al;
    int i = (blockIdx.x * blockDim.x + threadIdx.x) * 4;
    if (i >= n) return;
    float4 v = *(const float4*)&in[i];
    uint32_t h0, l0, h1, l1;
    split2(v.x, v.y, h0, l0);
    split2(v.z, v.w, h1, l1);
    *(uint32_t*)&hi[i]     = h0; *(uint32_t*)&hi[i + 2] = h1;
    *(uint32_t*)&lo[i]     = l0; *(uint32_t*)&lo[i + 2] = l1;
}

// transpose + split, 4 weights in one launch (z selects). in fp32 [DD][C] -> [C][DD]
__global__ void k_tsplit4(const float* __restrict__ i0, bf16* __restrict__ h0, bf16* __restrict__ l0,
                          const float* __restrict__ i1, bf16* __restrict__ h1, bf16* __restrict__ l1,
                          const float* __restrict__ i2, bf16* __restrict__ h2, bf16* __restrict__ l2,
                          const float* __restrict__ i3, bf16* __restrict__ h3, bf16* __restrict__ l3)
{
    const int z = blockIdx.z;
    const float* in = (z == 0) ? i0 : (z == 1) ? i1 : (z == 2) ? i2 : i3;
    bf16* hi = (z == 0) ? h0 : (z == 1) ? h1 : (z == 2) ? h2 : h3;
    bf16* lo = (z == 0) ? l0 : (z == 1) ? l1 : (z == 2) ? l2 : l3;
    const int C = (z < 2) ? DD : KVD;
    const int R = DD;
    int r0 = blockIdx.y * 32, c0 = blockIdx.x * 32;
    if (c0 >= C) return;
    __shared__ float t[32][33];
#pragma unroll
    for (int i = 0; i < 4; i++) {
        int r = r0 + threadIdx.y + i * 8;
        t[threadIdx.y + i * 8][threadIdx.x] = in[(size_t)r * C + c0 + threadIdx.x];
    }
    __syncthreads();
#pragma unroll
    for (int i = 0; i < 4; i++) {
        int c = c0 + threadIdx.y + i * 8;
        float v = t[threadIdx.x][threadIdx.y + i * 8];
        bf16 h, l; split_bf16(v, h, l);
        hi[(size_t)c * R + r0 + threadIdx.x] = h;
        lo[(size_t)c * R + r0 + threadIdx.x] = l;
    }
}

// ============================================================================
// Tensor-core GEMM on pre-split bf16 (R12 config: BM=BN=128, BK=32).
// Epilogue modes: 0 fp32 C, 1 split bf16 (with scale), 2 split bf16 V-T
// ============================================================================
#define BM 128
#define BN 128
#define BK 32
#define KSTR 40
#define TILE_BF (BM * KSTR)
#define STAGE_BF (4 * TILE_BF)
#define GEMM_SMEM (2 * STAGE_BF * 2)

__device__ __forceinline__ void stage_tiles(
    bf16* base, const bf16* Ah, const bf16* Al, const bf16* Bh, const bf16* Bl,
    int row0, int col0, int kt, int K, int tid)
{
    bf16* pAh = base;               bf16* pAl = base + TILE_BF;
    bf16* pBh = base + 2 * TILE_BF; bf16* pBl = base + 3 * TILE_BF;
#pragma unroll
    for (int p = 0; p < 2; p++) {
        int c   = tid + p * 256;
        int r   = c >> 2;
        int off = (c & 3) * 8;
        const size_t ga = (size_t)(row0 + r) * K + kt + off;
        const size_t gb = (size_t)(col0 + r) * K + kt + off;
        const int so = r * KSTR + off;
        cpa16(pAh + so, Ah + ga);
        cpa16(pAl + so, Al + ga);
        cpa16(pBh + so, Bh + gb);
        cpa16(pBl + so, Bl + gb);
    }
}

__global__ __launch_bounds__(256, 2)
void gemm_tc(const bf16* __restrict__ Ah, const bf16* __restrict__ Al,
             const bf16* __restrict__ B0h, const bf16* __restrict__ B0l,
             const float* __restrict__ b0, float* __restrict__ C0,
             bf16* __restrict__ C0h, bf16* __restrict__ C0l, int mode0,
             const bf16* __restrict__ B1h, const bf16* __restrict__ B1l,
             const float* __restrict__ b1, float* __restrict__ C1,
             bf16* __restrict__ C1h, bf16* __restrict__ C1l, int mode1,
             float scale, int M, int N, int K)
{
    const bf16* Bh   = blockIdx.z ? B1h : B0h;
    const bf16* Bl   = blockIdx.z ? B1l : B0l;
    const float* bias = blockIdx.z ? b1 : b0;
    float* C   = blockIdx.z ? C1 : C0;
    bf16*  Ch  = blockIdx.z ? C1h : C0h;
    bf16*  Cl  = blockIdx.z ? C1l : C0l;
    const int mode = blockIdx.z ? mode1 : mode0;

    extern __shared__ bf16 smem[];

    const int tid  = threadIdx.x;
    const int lane = tid & 31;
    const int wid  = tid >> 5;
    const int wm   = wid & 1;
    const int wn   = wid >> 1;
    const int row0 = blockIdx.y * BM;
    const int col0 = blockIdx.x * BN;

    float acc[4][4][4];
#pragma unroll
    for (int i = 0; i < 4; i++)
#pragma unroll
        for (int j = 0; j < 4; j++)
#pragma unroll
            for (int k = 0; k < 4; k++) acc[i][j][k] = 0.f;

    const int a_r = lane & 15;
    const int a_k = (lane >> 4) << 3;
    const int b_r = (lane & 7) | ((lane & 16) >> 1);
    const int b_k = lane & 8;

    const int nt = K / BK;

    stage_tiles(smem, Ah, Al, Bh, Bl, row0, col0, 0, K, tid);
    asm volatile("cp.async.commit_group;");

    for (int t = 0; t < nt; t++) {
        if (t + 1 < nt)
            stage_tiles(smem + ((t + 1) & 1) * STAGE_BF,
                        Ah, Al, Bh, Bl, row0, col0, (t + 1) * BK, K, tid);
        asm volatile("cp.async.commit_group;");
        asm volatile("cp.async.wait_group 1;");
        __syncthreads();

        bf16* base = smem + (t & 1) * STAGE_BF;
        bf16* pAh = base;             bf16* pAl = base + TILE_BF;
        bf16* pBh = base + 2*TILE_BF; bf16* pBl = base + 3*TILE_BF;

#pragma unroll
        for (int kk = 0; kk < BK; kk += 16) {
            uint32_t af[4][4], bh[2][4], bl[2][4];
#pragma unroll
            for (int i = 0; i < 4; i++)
                ldmx4(af[i], pAh + (wm * 64 + i * 16 + a_r) * KSTR + kk + a_k);
#pragma unroll
            for (int j = 0; j < 2; j++)
                ldmx4(bh[j], pBh + (wn * 32 + j * 16 + b_r) * KSTR + kk + b_k);
#pragma unroll
            for (int j = 0; j < 2; j++)
                ldmx4(bl[j], pBl + (wn * 32 + j * 16 + b_r) * KSTR + kk + b_k);

#pragma unroll
            for (int i = 0; i < 4; i++)
#pragma unroll
                for (int j = 0; j < 4; j++)
                    mma16816(acc[i][j], af[i], &bh[j >> 1][(j & 1) * 2]);
#pragma unroll
            for (int i = 0; i < 4; i++)
#pragma unroll
                for (int j = 0; j < 4; j++)
                    mma16816(acc[i][j], af[i], &bl[j >> 1][(j & 1) * 2]);
#pragma unroll
            for (int i = 0; i < 4; i++)
                ldmx4(af[i], pAl + (wm * 64 + i * 16 + a_r) * KSTR + kk + a_k);
#pragma unroll
            for (int i = 0; i < 4; i++)
#pragma unroll
                for (int j = 0; j < 4; j++)
                    mma16816(acc[i][j], af[i], &bh[j >> 1][(j & 1) * 2]);
        }
        __syncthreads();
    }

    // epilogue
#pragma unroll
    for (int i = 0; i < 4; i++) {
        int gr = row0 + wm * 64 + i * 16 + (lane >> 2);
#pragma unroll
        for (int j = 0; j < 4; j++) {
            int gc = col0 + wn * 32 + j * 8 + (lane & 3) * 2;
            float bx = bias[gc], by = bias[gc + 1];
            float v0 = (acc[i][j][0] + bx) * scale, v1 = (acc[i][j][1] + by) * scale;
            float v2 = (acc[i][j][2] + bx) * scale, v3 = (acc[i][j][3] + by) * scale;
            if (mode == 0) {
                *(float2*)&C[(size_t)gr * N + gc]       = make_float2(v0, v1);
                *(float2*)&C[(size_t)(gr + 8) * N + gc] = make_float2(v2, v3);
            } else if (mode == 1) {
                uint32_t hp0, lp0, hp1, lp1;
                split2(v0, v1, hp0, lp0);
                split2(v2, v3, hp1, lp1);
                *(uint32_t*)&Ch[(size_t)gr * N + gc]       = hp0;
                *(uint32_t*)&Cl[(size_t)gr * N + gc]       = lp0;
                *(uint32_t*)&Ch[(size_t)(gr + 8) * N + gc] = hp1;
                *(uint32_t*)&Cl[(size_t)(gr + 8) * N + gc] = lp1;
            } else {
                int b0i = gr >> 10, s0 = gr & 1023;
                int b1i = (gr + 8) >> 10, s1 = (gr + 8) & 1023;
                bf16 h, l;
                size_t i00 = ((size_t)b0i * KVD + gc) * SS + s0;
                size_t i01 = ((size_t)b0i * KVD + gc + 1) * SS + s0;
                size_t i10 = ((size_t)b1i * KVD + gc) * SS + s1;
                size_t i11 = ((size_t)b1i * KVD + gc + 1) * SS + s1;
                split_bf16(v0, h, l); Ch[i00] = h; Cl[i00] = l;
                split_bf16(v1, h, l); Ch[i01] = h; Cl[i01] = l;
                split_bf16(v2, h, l); Ch[i10] = h; Cl[i10] = l;
                split_bf16(v3, h, l); Ch[i11] = h; Cl[i11] = l;
            }
        }
    }
}

// ============================================================================
// Tensor-core causal GQA flash attention, double-buffered K/V pipeline,
// 2 CTAs/SM: Q-lo fragments live in persistent smem (reloaded per tile),
// __launch_bounds__(256, 2) caps regs at 128. y reversed for LPT scheduling.
// ============================================================================
#define QSTR 72
#define QLO_ELEMS (128 * QSTR)               // persistent Q-lo region
#define KVSTG (4 * 64 * QSTR)                // per-stage K/V elems
#define ATTN_SMEM ((QLO_ELEMS + 2 * KVSTG) * 2)   // 92160 B

__global__ __launch_bounds__(256, 2)
void attn_mma(const bf16* __restrict__ Qh, const bf16* __restrict__ Ql,
              const bf16* __restrict__ Kh, const bf16* __restrict__ Kl,
              const bf16* __restrict__ Vth, const bf16* __restrict__ Vtl,
              bf16* __restrict__ Aoh, bf16* __restrict__ Aol)
{
    extern __shared__ bf16 sm[];
    bf16* sQl = sm;                          // persistent [128][QSTR]
    bf16* kvb = sm + QLO_ELEMS;              // 2 K/V stages

    const int tid = threadIdx.x, lane = tid & 31, wid = tid >> 5;
    const int y  = (gridDim.x - 1) - blockIdx.x;   // LPT: heavy tiles first
    const int bh = blockIdx.y;
    const int b  = bh >> 5, h = bh & 31, kh = h >> 2;
    const int qtok0 = b * SS + y * 128;

    const int a_r = lane & 15;
    const int a_k = (lane >> 4) << 3;
    const int b_r = (lane & 7) | ((lane & 16) >> 1);
    const int b_k = lane & 8;

    // ---- stage Q: hi transient (into KV stage-0 area), lo persistent ----
    bf16* sQh_t = kvb;                       // transient, overwritten later
#pragma unroll
    for (int p = 0; p < 4; p++) {
        int c = tid + p * 256;
        int r = c >> 3, off = (c & 7) * 8;
        const size_t g = (size_t)(qtok0 + r) * DD + h * HD + off;
        cpa16(sQh_t + r * QSTR + off, Qh + g);
        cpa16(sQl   + r * QSTR + off, Ql + g);
    }
    asm volatile("cp.async.commit_group;");
    asm volatile("cp.async.wait_group 0;");
    __syncthreads();

    // Q-hi a-frags to registers (Q-lo stays in smem, reloaded per tile)
    uint32_t qah[4][4];
#pragma unroll
    for (int kk = 0; kk < 4; kk++)
        ldmx4(qah[kk], sQh_t + (wid * 16 + a_r) * QSTR + kk * 16 + a_k);
    __syncthreads();   // transient Q-hi region now free for K/V staging

    float oacc[8][4];
#pragma unroll
    for (int f = 0; f < 8; f++)
#pragma unroll
        for (int e = 0; e < 4; e++) oacc[f][e] = 0.f;
    float mA = -1e30f, mB = -1e30f, lA = 0.f, lB = 0.f;

    const int qrowA = y * 128 + wid * 16 + (lane >> 2);
    const int jend = 2 * y + 1;

    auto stage_kv = [&](int s, int j) {
        bf16* base = kvb + s * KVSTG;
        bf16* pKh = base;
        bf16* pKl = base + 64 * QSTR;
        bf16* pVh = base + 128 * QSTR;
        bf16* pVl = base + 192 * QSTR;
        const int ktok0 = b * SS + j * 64;
#pragma unroll
        for (int p = 0; p < 2; p++) {
            int c = tid + p * 256;
            int r = c >> 3, off = (c & 7) * 8;
            const size_t gk = (size_t)(ktok0 + r) * KVD + kh * HD + off;
            cpa16(pKh + r * QSTR + off, Kh + gk);
            cpa16(pKl + r * QSTR + off, Kl + gk);
            const size_t gv = ((size_t)b * KVD + kh * HD + r) * SS + j * 64 + off;
            cpa16(pVh + r * QSTR + off, Vth + gv);
            cpa16(pVl + r * QSTR + off, Vtl + gv);
        }
    };

    stage_kv(0, 0);
    asm volatile("cp.async.commit_group;");

    for (int j = 0; j <= jend; j++) {
        if (j + 1 <= jend)
            stage_kv((j + 1) & 1, j + 1);
        asm volatile("cp.async.commit_group;");
        asm volatile("cp.async.wait_group 1;");
        __syncthreads();

        bf16* base = kvb + (j & 1) * KVSTG;
        bf16* sKh = base;
        bf16* sKl = base + 64 * QSTR;
        bf16* sVh = base + 128 * QSTR;
        bf16* sVl = base + 192 * QSTR;

        if (j * 64 <= y * 128 + wid * 16 + 15) {
            // ---- S = Q K^T (Q pre-scaled), 3-term split ----
            float sacc[8][4];
#pragma unroll
            for (int f = 0; f < 8; f++)
#pragma unroll
                for (int e = 0; e < 4; e++) sacc[f][e] = 0.f;

            uint32_t kb[4][4];
#pragma unroll
            for (int kk = 0; kk < 4; kk++) {
#pragma unroll
                for (int nb = 0; nb < 4; nb++)
                    ldmx4(kb[nb], sKh + (nb * 16 + b_r) * QSTR + kk * 16 + b_k);
#pragma unroll
                for (int f = 0; f < 8; f++)
                    mma16816(sacc[f], qah[kk], &kb[f >> 1][(f & 1) * 2]);
                // Q-lo from persistent smem
                uint32_t qalk[4];
                ldmx4(qalk, sQl + (wid * 16 + a_r) * QSTR + kk * 16 + a_k);
#pragma unroll
                for (int f = 0; f < 8; f++)
                    mma16816(sacc[f], qalk, &kb[f >> 1][(f & 1) * 2]);
#pragma unroll
                for (int nb = 0; nb < 4; nb++)
                    ldmx4(kb[nb], sKl + (nb * 16 + b_r) * QSTR + kk * 16 + b_k);
#pragma unroll
                for (int f = 0; f < 8; f++)
                    mma16816(sacc[f], qah[kk], &kb[f >> 1][(f & 1) * 2]);
            }

            // ---- causal mask: only diagonal supertiles need it ----
            if (j >= 2 * y) {
#pragma unroll
                for (int f = 0; f < 8; f++)
#pragma unroll
                    for (int e = 0; e < 4; e++) {
                        int kg = j * 64 + f * 8 + (lane & 3) * 2 + (e & 1);
                        int qg = qrowA + (e >> 1) * 8;
                        if (kg > qg) sacc[f][e] = -1e30f;
                    }
            }

            // ---- online softmax (rows A: e0/e1, rows B: e2/e3) ----
            float tmA = -1e30f, tmB = -1e30f;
#pragma unroll
            for (int f = 0; f < 8; f++) {
                tmA = fmaxf(tmA, fmaxf(sacc[f][0], sacc[f][1]));
                tmB = fmaxf(tmB, fmaxf(sacc[f][2], sacc[f][3]));
            }
            tmA = fmaxf(tmA, __shfl_xor_sync(0xffffffffu, tmA, 1));
            tmA = fmaxf(tmA, __shfl_xor_sync(0xffffffffu, tmA, 2));
            tmB = fmaxf(tmB, __shfl_xor_sync(0xffffffffu, tmB, 1));
            tmB = fmaxf(tmB, __shfl_xor_sync(0xffffffffu, tmB, 2));
            float mnA = fmaxf(mA, tmA), mnB = fmaxf(mB, tmB);
            float alA = __expf(mA - mnA), alB = __expf(mB - mnB);
            mA = mnA; mB = mnB;

            float suA = 0.f, suB = 0.f;
#pragma unroll
            for (int f = 0; f < 8; f++) {
                float p0 = __expf(sacc[f][0] - mA);
                float p1 = __expf(sacc[f][1] - mA);
                float p2 = __expf(sacc[f][2] - mB);
                float p3 = __expf(sacc[f][3] - mB);
                suA += p0 + p1; suB += p2 + p3;
                sacc[f][0] = p0; sacc[f][1] = p1; sacc[f][2] = p2; sacc[f][3] = p3;
            }
            suA += __shfl_xor_sync(0xffffffffu, suA, 1);
            suA += __shfl_xor_sync(0xffffffffu, suA, 2);
            suB += __shfl_xor_sync(0xffffffffu, suB, 1);
            suB += __shfl_xor_sync(0xffffffffu, suB, 2);
            lA = lA * alA + suA; lB = lB * alB + suB;

#pragma unroll
            for (int f = 0; f < 8; f++) {
                oacc[f][0] *= alA; oacc[f][1] *= alA;
                oacc[f][2] *= alB; oacc[f][3] *= alB;
            }

            // ---- O += P V (per kc-chunk: packed split of P, MMA w/ Vt) ----
            uint32_t vb[4][4];
#pragma unroll
            for (int c = 0; c < 4; c++) {
                const int f0 = 2 * c, f1 = 2 * c + 1;
                uint32_t pah[4], pal[4];
                split2(sacc[f0][0], sacc[f0][1], pah[0], pal[0]);
                split2(sacc[f0][2], sacc[f0][3], pah[1], pal[1]);
                split2(sacc[f1][0], sacc[f1][1], pah[2], pal[2]);
                split2(sacc[f1][2], sacc[f1][3], pah[3], pal[3]);
#pragma unroll
                for (int nb = 0; nb < 4; nb++)
                    ldmx4(vb[nb], sVh + (nb * 16 + b_r) * QSTR + c * 16 + b_k);
#pragma unroll
                for (int f = 0; f < 8; f++)
                    mma16816(oacc[f], pah, &vb[f >> 1][(f & 1) * 2]);
#pragma unroll
                for (int f = 0; f < 8; f++)
                    mma16816(oacc[f], pal, &vb[f >> 1][(f & 1) * 2]);
#pragma unroll
                for (int nb = 0; nb < 4; nb++)
                    ldmx4(vb[nb], sVl + (nb * 16 + b_r) * QSTR + c * 16 + b_k);
#pragma unroll
                for (int f = 0; f < 8; f++)
                    mma16816(oacc[f], pah, &vb[f >> 1][(f & 1) * 2]);
            }
        }
        __syncthreads();
    }

    // ---- normalize + packed split-write O ----
    const float ivA = 1.f / lA, ivB = 1.f / lB;
    const int tokA = qtok0 + wid * 16 + (lane >> 2);
#pragma unroll
    for (int f = 0; f < 8; f++) {
        int col = h * HD + f * 8 + (lane & 3) * 2;
        uint32_t hpA, lpA, hpB, lpB;
        split2(oacc[f][0] * ivA, oacc[f][1] * ivA, hpA, lpA);
        split2(oacc[f][2] * ivB, oacc[f][3] * ivB, hpB, lpB);
        *(uint32_t*)&Aoh[(size_t)tokA * DD + col]       = hpA;
        *(uint32_t*)&Aol[(size_t)tokA * DD + col]       = lpA;
        *(uint32_t*)&Aoh[(size_t)(tokA + 8) * DD + col] = hpB;
        *(uint32_t*)&Aol[(size_t)(tokA + 8) * DD + col] = lpB;
    }
}

// ---------------- launcher ----------------
extern "C" void kernel_launch(void* const* d_in, const int* in_sizes, int n_in,
                              void* d_out, int out_size)
{
    const float* q  = (const float*)d_in[0];
    const float* kv = (const float*)d_in[1];
    // d_in[2] = mask (causal, static) -- unused
    const float* Wq = (const float*)d_in[3];
    const float* bq = (const float*)d_in[4];
    const float* Wk = (const float*)d_in[5];
    const float* bk = (const float*)d_in[6];
    const float* Wv = (const float*)d_in[7];
    const float* bv = (const float*)d_in[8];
    const float* Wo = (const float*)d_in[9];
    const float* bo = (const float*)d_in[10];
    float* out = (float*)d_out;

    bf16 *qh, *ql, *kvh, *kvl, *Wqth, *Wqtl, *Wkth, *Wktl, *Wvth_, *Wvtl_, *Woth, *Wotl;
    bf16 *Qsh, *Qsl, *Ksh, *Ksl, *Vth, *Vtl, *Aoh, *Aol;
    cudaGetSymbolAddress((void**)&qh,  g_qh);   cudaGetSymbolAddress((void**)&ql,  g_ql);
    cudaGetSymbolAddress((void**)&kvh, g_kvh);  cudaGetSymbolAddress((void**)&kvl, g_kvl);
    cudaGetSymbolAddress((void**)&Wqth, g_Wqt_h); cudaGetSymbolAddress((void**)&Wqtl, g_Wqt_l);
    cudaGetSymbolAddress((void**)&Wkth, g_Wkt_h); cudaGetSymbolAddress((void**)&Wktl, g_Wkt_l);
    cudaGetSymbolAddress((void**)&Wvth_, g_Wvt_h); cudaGetSymbolAddress((void**)&Wvtl_, g_Wvt_l);
    cudaGetSymbolAddress((void**)&Woth, g_Wot_h); cudaGetSymbolAddress((void**)&Wotl, g_Wot_l);
    cudaGetSymbolAddress((void**)&Qsh, g_Qsh);  cudaGetSymbolAddress((void**)&Qsl, g_Qsl);
    cudaGetSymbolAddress((void**)&Ksh, g_Ksh);  cudaGetSymbolAddress((void**)&Ksl, g_Ksl);
    cudaGetSymbolAddress((void**)&Vth, g_Vth);  cudaGetSymbolAddress((void**)&Vtl, g_Vtl);
    cudaGetSymbolAddress((void**)&Aoh, g_Aoh);  cudaGetSymbolAddress((void**)&Aol, g_Aol);

    cudaFuncSetAttribute(gemm_tc,
                         cudaFuncAttributeMaxDynamicSharedMemorySize, GEMM_SMEM);
    cudaFuncSetAttribute(attn_mma,
                         cudaFuncAttributeMaxDynamicSharedMemorySize, ATTN_SMEM);

    // ---- converts (2 fused launches) ----
    k_split2in<<<dim3(MTOT * DD / 4 / 256, 1, 2), 256>>>(
        q, qh, ql, kv, kvh, kvl, MTOT * DD);
    k_tsplit4<<<dim3(DD / 32, DD / 32, 4), dim3(32, 8)>>>(
        Wq, Wqth, Wqtl, Wo, Woth, Wotl, Wk, Wkth, Wktl, Wv, Wvth_, Wvtl_);

    // ---- Q projection -> split bf16, pre-scaled by 1/sqrt(HD)=0.125 ----
    gemm_tc<<<dim3(DD / BN, MTOT / BM, 1), 256, GEMM_SMEM>>>(
        qh, ql, Wqth, Wqtl, bq, nullptr, Qsh, Qsl, 1,
        Wqth, Wqtl, bq, nullptr, Qsh, Qsl, 1, 0.125f, MTOT, DD, DD);

    // ---- K (split natural) and V (split transposed) projections ----
    gemm_tc<<<dim3(KVD / BN, MTOT / BM, 2), 256, GEMM_SMEM>>>(
        kvh, kvl, Wkth, Wktl, bk, nullptr, Ksh, Ksl, 1,
        Wvth_, Wvtl_, bv, nullptr, Vth, Vtl, 2, 1.0f, MTOT, KVD, DD);

    // ---- tensor-core attention -> Ao split ----
    attn_mma<<<dim3(SS / 128, BB * QH), 256, ATTN_SMEM>>>(
        Qsh, Qsl, Ksh, Ksl, Vth, Vtl, Aoh, Aol);

    // ---- output projection (fp32 out) ----
    gemm_tc<<<dim3(DD / BN, MTOT / BM, 1), 256, GEMM_SMEM>>>(
        Aoh, Aol, Woth, Wotl, bo, out, nullptr, nullptr, 0,
        Woth, Wotl, bo, out, nullptr, nullptr, 0, 1.0f, MTOT, DD, DD);
}

// round 15
// speedup vs baseline: 1.0672x; 1.0275x over previous
#include <cuda_runtime.h>
#include <cuda_bf16.h>
#include <cstdint>

// Problem constants
#define BB   2
#define SS   1024
#define DD   2048
#define QH   32
#define KH   8
#define HD   64
#define KVD  (KH*HD)        // 512
#define MTOT (BB*SS)        // 2048

typedef __nv_bfloat16 bf16;
typedef __nv_bfloat162 bf162;

// ---------------- scratch (device globals; alignas(16) for cp.async) -------
__device__ alignas(16) bf16 g_qh[MTOT * DD],  g_ql[MTOT * DD];
__device__ alignas(16) bf16 g_kvh[MTOT * DD], g_kvl[MTOT * DD];
__device__ alignas(16) bf16 g_Wqt_h[DD * DD],  g_Wqt_l[DD * DD];     // [n][k]
__device__ alignas(16) bf16 g_Wkt_h[KVD * DD], g_Wkt_l[KVD * DD];
__device__ alignas(16) bf16 g_Wvt_h[KVD * DD], g_Wvt_l[KVD * DD];
__device__ alignas(16) bf16 g_Wot_h[DD * DD],  g_Wot_l[DD * DD];
__device__ alignas(16) bf16 g_Qsh[MTOT * DD],  g_Qsl[MTOT * DD];
__device__ alignas(16) bf16 g_Ksh[MTOT * KVD], g_Ksl[MTOT * KVD];
__device__ alignas(16) bf16 g_Vth[BB * KVD * SS], g_Vtl[BB * KVD * SS]; // V^T
__device__ alignas(16) bf16 g_Aoh[MTOT * DD], g_Aol[MTOT * DD];

__device__ __forceinline__ void split_bf16(float v, bf16& h, bf16& l) {
    h = __float2bfloat16_rn(v);
    l = __float2bfloat16_rn(v - __bfloat162float(h));
}
__device__ __forceinline__ uint32_t pack2(bf16 a, bf16 b) {
    bf162 t = __halves2bfloat162(a, b);
    return *(uint32_t*)&t;
}
// packed split of two floats: hp = pack2(bf(a), bf(b)), lp = pack2(residuals)
__device__ __forceinline__ void split2(float a, float b, uint32_t& hp, uint32_t& lp) {
    asm("cvt.rn.bf16x2.f32 %0, %1, %2;" : "=r"(hp) : "f"(b), "f"(a));
    float ha = __uint_as_float(hp << 16);
    float hb = __uint_as_float(hp & 0xFFFF0000u);
    float la = a - ha, lb = b - hb;
    asm("cvt.rn.bf16x2.f32 %0, %1, %2;" : "=r"(lp) : "f"(lb), "f"(la));
}
__device__ __forceinline__ void cpa16(void* dst, const void* src) {
    uint32_t d = (uint32_t)__cvta_generic_to_shared(dst);
    asm volatile("cp.async.ca.shared.global [%0], [%1], 16;" :: "r"(d), "l"(src));
}
__device__ __forceinline__ void ldmx4(uint32_t* r, const void* p) {
    uint32_t addr = (uint32_t)__cvta_generic_to_shared(p);
    asm volatile("ldmatrix.sync.aligned.m8n8.x4.shared.b16 {%0,%1,%2,%3}, [%4];"
                 : "=r"(r[0]), "=r"(r[1]), "=r"(r[2]), "=r"(r[3]) : "r"(addr));
}
__device__ __forceinline__ void mma16816(float* c, const uint32_t* a, const uint32_t* b) {
    asm volatile("mma.sync.aligned.m16n8k16.row.col.f32.bf16.bf16.f32 "
                 "{%0,%1,%2,%3}, {%4,%5,%6,%7}, {%8,%9}, {%0,%1,%2,%3};"
                 : "+f"(c[0]), "+f"(c[1]), "+f"(c[2]), "+f"(c[3])
                 : "r"(a[0]), "r"(a[1]), "r"(a[2]), "r"(a[3]),
                   "r"(b[0]), "r"(b[1]));
}

// ---------------- convert kernels (fused) ----------------
__global__ void k_split2in(const float* __restrict__ a, bf16* __restrict__ ah, bf16* __restrict__ al,
                           const float* __restrict__ b, bf16* __restrict__ bh, bf16* __restrict__ bl,
                           int n)
{
    const float* in = blockIdx.z ? b : a;
    bf16* hi = blockIdx.z ? bh : ah;
    bf16* lo = blockIdx.z ? bl : al;
    int i = (blockIdx.x * blockDim.x + threadIdx.x) * 4;
    if (i >= n) return;
    float4 v = *(const float4*)&in[i];
    uint32_t h0, l0, h1, l1;
    split2(v.x, v.y, h0, l0);
    split2(v.z, v.w, h1, l1);
    *(uint32_t*)&hi[i]     = h0; *(uint32_t*)&hi[i + 2] = h1;
    *(uint32_t*)&lo[i]     = l0; *(uint32_t*)&lo[i + 2] = l1;
}

// transpose + split, 4 weights in one launch (z selects). in fp32 [DD][C] -> [C][DD]
__global__ void k_tsplit4(const float* __restrict__ i0, bf16* __restrict__ h0, bf16* __restrict__ l0,
                          const float* __restrict__ i1, bf16* __restrict__ h1, bf16* __restrict__ l1,
                          const float* __restrict__ i2, bf16* __restrict__ h2, bf16* __restrict__ l2,
                          const float* __restrict__ i3, bf16* __restrict__ h3, bf16* __restrict__ l3)
{
    const int z = blockIdx.z;
    const float* in = (z == 0) ? i0 : (z == 1) ? i1 : (z == 2) ? i2 : i3;
    bf16* hi = (z == 0) ? h0 : (z == 1) ? h1 : (z == 2) ? h2 : h3;
    bf16* lo = (z == 0) ? l0 : (z == 1) ? l1 : (z == 2) ? l2 : l3;
    const int C = (z < 2) ? DD : KVD;
    const int R = DD;
    int r0 = blockIdx.y * 32, c0 = blockIdx.x * 32;
    if (c0 >= C) return;
    __shared__ float t[32][33];
#pragma unroll
    for (int i = 0; i < 4; i++) {
        int r = r0 + threadIdx.y + i * 8;
        t[threadIdx.y + i * 8][threadIdx.x] = in[(size_t)r * C + c0 + threadIdx.x];
    }
    __syncthreads();
#pragma unroll
    for (int i = 0; i < 4; i++) {
        int c = c0 + threadIdx.y + i * 8;
        float v = t[threadIdx.x][threadIdx.y + i * 8];
        bf16 h, l; split_bf16(v, h, l);
        hi[(size_t)c * R + r0 + threadIdx.x] = h;
        lo[(size_t)c * R + r0 + threadIdx.x] = l;
    }
}

// ============================================================================
// Tensor-core GEMM on pre-split bf16 (BM=BN=128, BK=32), multi-config:
// blockIdx.z selects one of three GemmCfg (Q/K/V projections fused in one
// launch). Early-exit for z-slices narrower than gridDim.x*BN.
// Epilogue modes: 0 fp32 C, 1 split bf16 (with scale), 2 split bf16 V-T
// ============================================================================
#define BM 128
#define BN 128
#define BK 32
#define KSTR 40
#define TILE_BF (BM * KSTR)
#define STAGE_BF (4 * TILE_BF)
#define GEMM_SMEM (2 * STAGE_BF * 2)

struct GemmCfg {
    const bf16 *Ah, *Al, *Bh, *Bl;
    const float* bias;
    float* C;
    bf16 *Ch, *Cl;
    int   mode;
    float scale;
    int   N;
};

__device__ __forceinline__ void stage_tiles(
    bf16* base, const bf16* Ah, const bf16* Al, const bf16* Bh, const bf16* Bl,
    int row0, int col0, int kt, int K, int tid)
{
    bf16* pAh = base;               bf16* pAl = base + TILE_BF;
    bf16* pBh = base + 2 * TILE_BF; bf16* pBl = base + 3 * TILE_BF;
#pragma unroll
    for (int p = 0; p < 2; p++) {
        int c   = tid + p * 256;
        int r   = c >> 2;
        int off = (c & 3) * 8;
        const size_t ga = (size_t)(row0 + r) * K + kt + off;
        const size_t gb = (size_t)(col0 + r) * K + kt + off;
        const int so = r * KSTR + off;
        cpa16(pAh + so, Ah + ga);
        cpa16(pAl + so, Al + ga);
        cpa16(pBh + so, Bh + gb);
        cpa16(pBl + so, Bl + gb);
    }
}

__global__ __launch_bounds__(256, 2)
void gemm_tc(GemmCfg c0, GemmCfg c1, GemmCfg c2, int M, int K)
{
    const GemmCfg cf = (blockIdx.z == 0) ? c0 : (blockIdx.z == 1) ? c1 : c2;
    const int N = cf.N;
    if ((int)blockIdx.x * BN >= N) return;   // narrow z-slice: idle CTA

    extern __shared__ bf16 smem[];

    const int tid  = threadIdx.x;
    const int lane = tid & 31;
    const int wid  = tid >> 5;
    const int wm   = wid & 1;
    const int wn   = wid >> 1;
    const int row0 = blockIdx.y * BM;
    const int col0 = blockIdx.x * BN;

    float acc[4][4][4];
#pragma unroll
    for (int i = 0; i < 4; i++)
#pragma unroll
        for (int j = 0; j < 4; j++)
#pragma unroll
            for (int k = 0; k < 4; k++) acc[i][j][k] = 0.f;

    const int a_r = lane & 15;
    const int a_k = (lane >> 4) << 3;
    const int b_r = (lane & 7) | ((lane & 16) >> 1);
    const int b_k = lane & 8;

    const int nt = K / BK;

    stage_tiles(smem, cf.Ah, cf.Al, cf.Bh, cf.Bl, row0, col0, 0, K, tid);
    asm volatile("cp.async.commit_group;");

    for (int t = 0; t < nt; t++) {
        if (t + 1 < nt)
            stage_tiles(smem + ((t + 1) & 1) * STAGE_BF,
                        cf.Ah, cf.Al, cf.Bh, cf.Bl, row0, col0, (t + 1) * BK, K, tid);
        asm volatile("cp.async.commit_group;");
        asm volatile("cp.async.wait_group 1;");
        __syncthreads();

        bf16* base = smem + (t & 1) * STAGE_BF;
        bf16* pAh = base;             bf16* pAl = base + TILE_BF;
        bf16* pBh = base + 2*TILE_BF; bf16* pBl = base + 3*TILE_BF;

#pragma unroll
        for (int kk = 0; kk < BK; kk += 16) {
            uint32_t af[4][4], bh[2][4], bl[2][4];
#pragma unroll
            for (int i = 0; i < 4; i++)
                ldmx4(af[i], pAh + (wm * 64 + i * 16 + a_r) * KSTR + kk + a_k);
#pragma unroll
            for (int j = 0; j < 2; j++)
                ldmx4(bh[j], pBh + (wn * 32 + j * 16 + b_r) * KSTR + kk + b_k);
#pragma unroll
            for (int j = 0; j < 2; j++)
                ldmx4(bl[j], pBl + (wn * 32 + j * 16 + b_r) * KSTR + kk + b_k);

#pragma unroll
            for (int i = 0; i < 4; i++)
#pragma unroll
                for (int j = 0; j < 4; j++)
                    mma16816(acc[i][j], af[i], &bh[j >> 1][(j & 1) * 2]);
#pragma unroll
            for (int i = 0; i < 4; i++)
#pragma unroll
                for (int j = 0; j < 4; j++)
                    mma16816(acc[i][j], af[i], &bl[j >> 1][(j & 1) * 2]);
#pragma unroll
            for (int i = 0; i < 4; i++)
                ldmx4(af[i], pAl + (wm * 64 + i * 16 + a_r) * KSTR + kk + a_k);
#pragma unroll
            for (int i = 0; i < 4; i++)
#pragma unroll
                for (int j = 0; j < 4; j++)
                    mma16816(acc[i][j], af[i], &bh[j >> 1][(j & 1) * 2]);
        }
        __syncthreads();
    }

    // epilogue
#pragma unroll
    for (int i = 0; i < 4; i++) {
        int gr = row0 + wm * 64 + i * 16 + (lane >> 2);
#pragma unroll
        for (int j = 0; j < 4; j++) {
            int gc = col0 + wn * 32 + j * 8 + (lane & 3) * 2;
            float bx = cf.bias[gc], by = cf.bias[gc + 1];
            float v0 = (acc[i][j][0] + bx) * cf.scale, v1 = (acc[i][j][1] + by) * cf.scale;
            float v2 = (acc[i][j][2] + bx) * cf.scale, v3 = (acc[i][j][3] + by) * cf.scale;
            if (cf.mode == 0) {
                *(float2*)&cf.C[(size_t)gr * N + gc]       = make_float2(v0, v1);
                *(float2*)&cf.C[(size_t)(gr + 8) * N + gc] = make_float2(v2, v3);
            } else if (cf.mode == 1) {
                uint32_t hp0, lp0, hp1, lp1;
                split2(v0, v1, hp0, lp0);
                split2(v2, v3, hp1, lp1);
                *(uint32_t*)&cf.Ch[(size_t)gr * N + gc]       = hp0;
                *(uint32_t*)&cf.Cl[(size_t)gr * N + gc]       = lp0;
                *(uint32_t*)&cf.Ch[(size_t)(gr + 8) * N + gc] = hp1;
                *(uint32_t*)&cf.Cl[(size_t)(gr + 8) * N + gc] = lp1;
            } else {
                int b0i = gr >> 10, s0 = gr & 1023;
                int b1i = (gr + 8) >> 10, s1 = (gr + 8) & 1023;
                bf16 h, l;
                size_t i00 = ((size_t)b0i * KVD + gc) * SS + s0;
                size_t i01 = ((size_t)b0i * KVD + gc + 1) * SS + s0;
                size_t i10 = ((size_t)b1i * KVD + gc) * SS + s1;
                size_t i11 = ((size_t)b1i * KVD + gc + 1) * SS + s1;
                split_bf16(v0, h, l); cf.Ch[i00] = h; cf.Cl[i00] = l;
                split_bf16(v1, h, l); cf.Ch[i01] = h; cf.Cl[i01] = l;
                split_bf16(v2, h, l); cf.Ch[i10] = h; cf.Cl[i10] = l;
                split_bf16(v3, h, l); cf.Ch[i11] = h; cf.Cl[i11] = l;
            }
        }
    }
}

// ============================================================================
// Tensor-core causal GQA flash attention (unchanged from R14: 2 CTAs/SM,
// Q-lo persistent in smem, double-buffered K/V, LPT y-order).
// ============================================================================
#define QSTR 72
#define QLO_ELEMS (128 * QSTR)
#define KVSTG (4 * 64 * QSTR)
#define ATTN_SMEM ((QLO_ELEMS + 2 * KVSTG) * 2)   // 92160 B

__global__ __launch_bounds__(256, 2)
void attn_mma(const bf16* __restrict__ Qh, const bf16* __restrict__ Ql,
              const bf16* __restrict__ Kh, const bf16* __restrict__ Kl,
              const bf16* __restrict__ Vth, const bf16* __restrict__ Vtl,
              bf16* __restrict__ Aoh, bf16* __restrict__ Aol)
{
    extern __shared__ bf16 sm[];
    bf16* sQl = sm;                          // persistent [128][QSTR]
    bf16* kvb = sm + QLO_ELEMS;              // 2 K/V stages

    const int tid = threadIdx.x, lane = tid & 31, wid = tid >> 5;
    const int y  = (gridDim.x - 1) - blockIdx.x;   // LPT: heavy tiles first
    const int bh = blockIdx.y;
    const int b  = bh >> 5, h = bh & 31, kh = h >> 2;
    const int qtok0 = b * SS + y * 128;

    const int a_r = lane & 15;
    const int a_k = (lane >> 4) << 3;
    const int b_r = (lane & 7) | ((lane & 16) >> 1);
    const int b_k = lane & 8;

    // ---- stage Q: hi transient (into KV stage-0 area), lo persistent ----
    bf16* sQh_t = kvb;
#pragma unroll
    for (int p = 0; p < 4; p++) {
        int c = tid + p * 256;
        int r = c >> 3, off = (c & 7) * 8;
        const size_t g = (size_t)(qtok0 + r) * DD + h * HD + off;
        cpa16(sQh_t + r * QSTR + off, Qh + g);
        cpa16(sQl   + r * QSTR + off, Ql + g);
    }
    asm volatile("cp.async.commit_group;");
    asm volatile("cp.async.wait_group 0;");
    __syncthreads();

    uint32_t qah[4][4];
#pragma unroll
    for (int kk = 0; kk < 4; kk++)
        ldmx4(qah[kk], sQh_t + (wid * 16 + a_r) * QSTR + kk * 16 + a_k);
    __syncthreads();

    float oacc[8][4];
#pragma unroll
    for (int f = 0; f < 8; f++)
#pragma unroll
        for (int e = 0; e < 4; e++) oacc[f][e] = 0.f;
    float mA = -1e30f, mB = -1e30f, lA = 0.f, lB = 0.f;

    const int qrowA = y * 128 + wid * 16 + (lane >> 2);
    const int jend = 2 * y + 1;

    auto stage_kv = [&](int s, int j) {
        bf16* base = kvb + s * KVSTG;
        bf16* pKh = base;
        bf16* pKl = base + 64 * QSTR;
        bf16* pVh = base + 128 * QSTR;
        bf16* pVl = base + 192 * QSTR;
        const int ktok0 = b * SS + j * 64;
#pragma unroll
        for (int p = 0; p < 2; p++) {
            int c = tid + p * 256;
            int r = c >> 3, off = (c & 7) * 8;
            const size_t gk = (size_t)(ktok0 + r) * KVD + kh * HD + off;
            cpa16(pKh + r * QSTR + off, Kh + gk);
            cpa16(pKl + r * QSTR + off, Kl + gk);
            const size_t gv = ((size_t)b * KVD + kh * HD + r) * SS + j * 64 + off;
            cpa16(pVh + r * QSTR + off, Vth + gv);
            cpa16(pVl + r * QSTR + off, Vtl + gv);
        }
    };

    stage_kv(0, 0);
    asm volatile("cp.async.commit_group;");

    for (int j = 0; j <= jend; j++) {
        if (j + 1 <= jend)
            stage_kv((j + 1) & 1, j + 1);
        asm volatile("cp.async.commit_group;");
        asm volatile("cp.async.wait_group 1;");
        __syncthreads();

        bf16* base = kvb + (j & 1) * KVSTG;
        bf16* sKh = base;
        bf16* sKl = base + 64 * QSTR;
        bf16* sVh = base + 128 * QSTR;
        bf16* sVl = base + 192 * QSTR;

        if (j * 64 <= y * 128 + wid * 16 + 15) {
            float sacc[8][4];
#pragma unroll
            for (int f = 0; f < 8; f++)
#pragma unroll
                for (int e = 0; e < 4; e++) sacc[f][e] = 0.f;

            uint32_t kb[4][4];
#pragma unroll
            for (int kk = 0; kk < 4; kk++) {
#pragma unroll
                for (int nb = 0; nb < 4; nb++)
                    ldmx4(kb[nb], sKh + (nb * 16 + b_r) * QSTR + kk * 16 + b_k);
#pragma unroll
                for (int f = 0; f < 8; f++)
                    mma16816(sacc[f], qah[kk], &kb[f >> 1][(f & 1) * 2]);
                uint32_t qalk[4];
                ldmx4(qalk, sQl + (wid * 16 + a_r) * QSTR + kk * 16 + a_k);
#pragma unroll
                for (int f = 0; f < 8; f++)
                    mma16816(sacc[f], qalk, &kb[f >> 1][(f & 1) * 2]);
#pragma unroll
                for (int nb = 0; nb < 4; nb++)
                    ldmx4(kb[nb], sKl + (nb * 16 + b_r) * QSTR + kk * 16 + b_k);
#pragma unroll
                for (int f = 0; f < 8; f++)
                    mma16816(sacc[f], qah[kk], &kb[f >> 1][(f & 1) * 2]);
            }

            if (j >= 2 * y) {
#pragma unroll
                for (int f = 0; f < 8; f++)
#pragma unroll
                    for (int e = 0; e < 4; e++) {
                        int kg = j * 64 + f * 8 + (lane & 3) * 2 + (e & 1);
                        int qg = qrowA + (e >> 1) * 8;
                        if (kg > qg) sacc[f][e] = -1e30f;
                    }
            }

            float tmA = -1e30f, tmB = -1e30f;
#pragma unroll
            for (int f = 0; f < 8; f++) {
                tmA = fmaxf(tmA, fmaxf(sacc[f][0], sacc[f][1]));
                tmB = fmaxf(tmB, fmaxf(sacc[f][2], sacc[f][3]));
            }
            tmA = fmaxf(tmA, __shfl_xor_sync(0xffffffffu, tmA, 1));
            tmA = fmaxf(tmA, __shfl_xor_sync(0xffffffffu, tmA, 2));
            tmB = fmaxf(tmB, __shfl_xor_sync(0xffffffffu, tmB, 1));
            tmB = fmaxf(tmB, __shfl_xor_sync(0xffffffffu, tmB, 2));
            float mnA = fmaxf(mA, tmA), mnB = fmaxf(mB, tmB);
            float alA = __expf(mA - mnA), alB = __expf(mB - mnB);
            mA = mnA; mB = mnB;

            float suA = 0.f, suB = 0.f;
#pragma unroll
            for (int f = 0; f < 8; f++) {
                float p0 = __expf(sacc[f][0] - mA);
                float p1 = __expf(sacc[f][1] - mA);
                float p2 = __expf(sacc[f][2] - mB);
                float p3 = __expf(sacc[f][3] - mB);
                suA += p0 + p1; suB += p2 + p3;
                sacc[f][0] = p0; sacc[f][1] = p1; sacc[f][2] = p2; sacc[f][3] = p3;
            }
            suA += __shfl_xor_sync(0xffffffffu, suA, 1);
            suA += __shfl_xor_sync(0xffffffffu, suA, 2);
            suB += __shfl_xor_sync(0xffffffffu, suB, 1);
            suB += __shfl_xor_sync(0xffffffffu, suB, 2);
            lA = lA * alA + suA; lB = lB * alB + suB;

#pragma unroll
            for (int f = 0; f < 8; f++) {
                oacc[f][0] *= alA; oacc[f][1] *= alA;
                oacc[f][2] *= alB; oacc[f][3] *= alB;
            }

            uint32_t vb[4][4];
#pragma unroll
            for (int c = 0; c < 4; c++) {
                const int f0 = 2 * c, f1 = 2 * c + 1;
                uint32_t pah[4], pal[4];
                split2(sacc[f0][0], sacc[f0][1], pah[0], pal[0]);
                split2(sacc[f0][2], sacc[f0][3], pah[1], pal[1]);
                split2(sacc[f1][0], sacc[f1][1], pah[2], pal[2]);
                split2(sacc[f1][2], sacc[f1][3], pah[3], pal[3]);
#pragma unroll
                for (int nb = 0; nb < 4; nb++)
                    ldmx4(vb[nb], sVh + (nb * 16 + b_r) * QSTR + c * 16 + b_k);
#pragma unroll
                for (int f = 0; f < 8; f++)
                    mma16816(oacc[f], pah, &vb[f >> 1][(f & 1) * 2]);
#pragma unroll
                for (int f = 0; f < 8; f++)
                    mma16816(oacc[f], pal, &vb[f >> 1][(f & 1) * 2]);
#pragma unroll
                for (int nb = 0; nb < 4; nb++)
                    ldmx4(vb[nb], sVl + (nb * 16 + b_r) * QSTR + c * 16 + b_k);
#pragma unroll
                for (int f = 0; f < 8; f++)
                    mma16816(oacc[f], pah, &vb[f >> 1][(f & 1) * 2]);
            }
        }
        __syncthreads();
    }

    const float ivA = 1.f / lA, ivB = 1.f / lB;
    const int tokA = qtok0 + wid * 16 + (lane >> 2);
#pragma unroll
    for (int f = 0; f < 8; f++) {
        int col = h * HD + f * 8 + (lane & 3) * 2;
        uint32_t hpA, lpA, hpB, lpB;
        split2(oacc[f][0] * ivA, oacc[f][1] * ivA, hpA, lpA);
        split2(oacc[f][2] * ivB, oacc[f][3] * ivB, hpB, lpB);
        *(uint32_t*)&Aoh[(size_t)tokA * DD + col]       = hpA;
        *(uint32_t*)&Aol[(size_t)tokA * DD + col]       = lpA;
        *(uint32_t*)&Aoh[(size_t)(tokA + 8) * DD + col] = hpB;
        *(uint32_t*)&Aol[(size_t)(tokA + 8) * DD + col] = lpB;
    }
}

// ---------------- launcher ----------------
extern "C" void kernel_launch(void* const* d_in, const int* in_sizes, int n_in,
                              void* d_out, int out_size)
{
    const float* q  = (const float*)d_in[0];
    const float* kv = (const float*)d_in[1];
    // d_in[2] = mask (causal, static) -- unused
    const float* Wq = (const float*)d_in[3];
    const float* bq = (const float*)d_in[4];
    const float* Wk = (const float*)d_in[5];
    const float* bk = (const float*)d_in[6];
    const float* Wv = (const float*)d_in[7];
    const float* bv = (const float*)d_in[8];
    const float* Wo = (const float*)d_in[9];
    const float* bo = (const float*)d_in[10];
    float* out = (float*)d_out;

    bf16 *qh, *ql, *kvh, *kvl, *Wqth, *Wqtl, *Wkth, *Wktl, *Wvth_, *Wvtl_, *Woth, *Wotl;
    bf16 *Qsh, *Qsl, *Ksh, *Ksl, *Vth, *Vtl, *Aoh, *Aol;
    cudaGetSymbolAddress((void**)&qh,  g_qh);   cudaGetSymbolAddress((void**)&ql,  g_ql);
    cudaGetSymbolAddress((void**)&kvh, g_kvh);  cudaGetSymbolAddress((void**)&kvl, g_kvl);
    cudaGetSymbolAddress((void**)&Wqth, g_Wqt_h); cudaGetSymbolAddress((void**)&Wqtl, g_Wqt_l);
    cudaGetSymbolAddress((void**)&Wkth, g_Wkt_h); cudaGetSymbolAddress((void**)&Wktl, g_Wkt_l);
    cudaGetSymbolAddress((void**)&Wvth_, g_Wvt_h); cudaGetSymbolAddress((void**)&Wvtl_, g_Wvt_l);
    cudaGetSymbolAddress((void**)&Woth, g_Wot_h); cudaGetSymbolAddress((void**)&Wotl, g_Wot_l);
    cudaGetSymbolAddress((void**)&Qsh, g_Qsh);  cudaGetSymbolAddress((void**)&Qsl, g_Qsl);
    cudaGetSymbolAddress((void**)&Ksh, g_Ksh);  cudaGetSymbolAddress((void**)&Ksl, g_Ksl);
    cudaGetSymbolAddress((void**)&Vth, g_Vth);  cudaGetSymbolAddress((void**)&Vtl, g_Vtl);
    cudaGetSymbolAddress((void**)&Aoh, g_Aoh);  cudaGetSymbolAddress((void**)&Aol, g_Aol);

    cudaFuncSetAttribute(gemm_tc,
                         cudaFuncAttributeMaxDynamicSharedMemorySize, GEMM_SMEM);
    cudaFuncSetAttribute(attn_mma,
                         cudaFuncAttributeMaxDynamicSharedMemorySize, ATTN_SMEM);

    // ---- converts (2 fused launches) ----
    k_split2in<<<dim3(MTOT * DD / 4 / 256, 1, 2), 256>>>(
        q, qh, ql, kv, kvh, kvl, MTOT * DD);
    k_tsplit4<<<dim3(DD / 32, DD / 32, 4), dim3(32, 8)>>>(
        Wq, Wqth, Wqtl, Wo, Woth, Wotl, Wk, Wkth, Wktl, Wv, Wvth_, Wvtl_);

    // ---- Q + K + V projections fused in ONE launch (z selects cfg) ----
    GemmCfg cq { qh,  ql,  Wqth,  Wqtl,  bq, nullptr, Qsh, Qsl, 1, 0.125f, DD  };
    GemmCfg ck { kvh, kvl, Wkth,  Wktl,  bk, nullptr, Ksh, Ksl, 1, 1.0f,   KVD };
    GemmCfg cv { kvh, kvl, Wvth_, Wvtl_, bv, nullptr, Vth, Vtl, 2, 1.0f,   KVD };
    gemm_tc<<<dim3(DD / BN, MTOT / BM, 3), 256, GEMM_SMEM>>>(cq, ck, cv, MTOT, DD);

    // ---- tensor-core attention -> Ao split ----
    attn_mma<<<dim3(SS / 128, BB * QH), 256, ATTN_SMEM>>>(
        Qsh, Qsl, Ksh, Ksl, Vth, Vtl, Aoh, Aol);

    // ---- output projection (fp32 out) ----
    GemmCfg co { Aoh, Aol, Woth, Wotl, bo, out, nullptr, nullptr, 0, 1.0f, DD };
    gemm_tc<<<dim3(DD / BN, MTOT / BM, 1), 256, GEMM_SMEM>>>(co, co, co, MTOT, DD);
}

// round 16
// speedup vs baseline: 1.0739x; 1.0062x over previous
#include <cuda_runtime.h>
#include <cuda_bf16.h>
#include <cstdint>

// Problem constants
#define BB   2
#define SS   1024
#define DD   2048
#define QH   32
#define KH   8
#define HD   64
#define KVD  (KH*HD)        // 512
#define MTOT (BB*SS)        // 2048

typedef __nv_bfloat16 bf16;
typedef __nv_bfloat162 bf162;

// ---------------- scratch (device globals; alignas(16) for cp.async) -------
__device__ alignas(16) bf16 g_qh[MTOT * DD],  g_ql[MTOT * DD];
__device__ alignas(16) bf16 g_kvh[MTOT * DD], g_kvl[MTOT * DD];
__device__ alignas(16) bf16 g_Wqt_h[DD * DD],  g_Wqt_l[DD * DD];     // [n][k]
__device__ alignas(16) bf16 g_Wkt_h[KVD * DD], g_Wkt_l[KVD * DD];
__device__ alignas(16) bf16 g_Wvt_h[KVD * DD], g_Wvt_l[KVD * DD];
__device__ alignas(16) bf16 g_Wot_h[DD * DD],  g_Wot_l[DD * DD];
__device__ alignas(16) bf16 g_Qsh[MTOT * DD],  g_Qsl[MTOT * DD];
__device__ alignas(16) bf16 g_Ksh[MTOT * KVD], g_Ksl[MTOT * KVD];
__device__ alignas(16) bf16 g_Vth[BB * KVD * SS], g_Vtl[BB * KVD * SS]; // V^T
__device__ alignas(16) bf16 g_Aoh[MTOT * DD], g_Aol[MTOT * DD];

__device__ __forceinline__ void split_bf16(float v, bf16& h, bf16& l) {
    h = __float2bfloat16_rn(v);
    l = __float2bfloat16_rn(v - __bfloat162float(h));
}
__device__ __forceinline__ uint32_t pack2(bf16 a, bf16 b) {
    bf162 t = __halves2bfloat162(a, b);
    return *(uint32_t*)&t;
}
// packed split of two floats: hp = pack2(bf(a), bf(b)), lp = pack2(residuals)
__device__ __forceinline__ void split2(float a, float b, uint32_t& hp, uint32_t& lp) {
    asm("cvt.rn.bf16x2.f32 %0, %1, %2;" : "=r"(hp) : "f"(b), "f"(a));
    float ha = __uint_as_float(hp << 16);
    float hb = __uint_as_float(hp & 0xFFFF0000u);
    float la = a - ha, lb = b - hb;
    asm("cvt.rn.bf16x2.f32 %0, %1, %2;" : "=r"(lp) : "f"(lb), "f"(la));
}
__device__ __forceinline__ float ex2(float x) {
    float y; asm("ex2.approx.f32 %0, %1;" : "=f"(y) : "f"(x)); return y;
}
__device__ __forceinline__ void cpa16(void* dst, const void* src) {
    uint32_t d = (uint32_t)__cvta_generic_to_shared(dst);
    asm volatile("cp.async.ca.shared.global [%0], [%1], 16;" :: "r"(d), "l"(src));
}
__device__ __forceinline__ void ldmx4(uint32_t* r, const void* p) {
    uint32_t addr = (uint32_t)__cvta_generic_to_shared(p);
    asm volatile("ldmatrix.sync.aligned.m8n8.x4.shared.b16 {%0,%1,%2,%3}, [%4];"
                 : "=r"(r[0]), "=r"(r[1]), "=r"(r[2]), "=r"(r[3]) : "r"(addr));
}
__device__ __forceinline__ void mma16816(float* c, const uint32_t* a, const uint32_t* b) {
    asm volatile("mma.sync.aligned.m16n8k16.row.col.f32.bf16.bf16.f32 "
                 "{%0,%1,%2,%3}, {%4,%5,%6,%7}, {%8,%9}, {%0,%1,%2,%3};"
                 : "+f"(c[0]), "+f"(c[1]), "+f"(c[2]), "+f"(c[3])
                 : "r"(a[0]), "r"(a[1]), "r"(a[2]), "r"(a[3]),
                   "r"(b[0]), "r"(b[1]));
}

// ============================================================================
// Fused convert kernel: grid (64, 64, 6), 256 threads.
//   z 0..1: elementwise split of q / kv (block idx = by*64+bx)
//   z 2..5: transpose+split of Wq / Wo / Wk / Wv
// ============================================================================
__global__ void k_conv(const float* __restrict__ q,  bf16* __restrict__ qh,  bf16* __restrict__ ql,
                       const float* __restrict__ kv, bf16* __restrict__ kvh, bf16* __restrict__ kvl,
                       const float* __restrict__ w0, bf16* __restrict__ w0h, bf16* __restrict__ w0l,
                       const float* __restrict__ w1, bf16* __restrict__ w1h, bf16* __restrict__ w1l,
                       const float* __restrict__ w2, bf16* __restrict__ w2h, bf16* __restrict__ w2l,
                       const float* __restrict__ w3, bf16* __restrict__ w3h, bf16* __restrict__ w3l)
{
    const int z = blockIdx.z;
    const int tid = threadIdx.x;
    if (z < 2) {
        const float* in = z ? kv : q;
        bf16* hi = z ? kvh : qh;
        bf16* lo = z ? kvl : ql;
        int blk = blockIdx.y * 64 + blockIdx.x;        // 0..4095
        int i = (blk * 256 + tid) * 4;                 // < MTOT*DD
        float4 v = *(const float4*)&in[i];
        uint32_t h0, l0, h1, l1;
        split2(v.x, v.y, h0, l0);
        split2(v.z, v.w, h1, l1);
        *(uint32_t*)&hi[i]     = h0; *(uint32_t*)&hi[i + 2] = h1;
        *(uint32_t*)&lo[i]     = l0; *(uint32_t*)&lo[i + 2] = l1;
        return;
    }
    const int w = z - 2;
    const float* in = (w == 0) ? w0 : (w == 1) ? w1 : (w == 2) ? w2 : w3;
    bf16* hi = (w == 0) ? w0h : (w == 1) ? w1h : (w == 2) ? w2h : w3h;
    bf16* lo = (w == 0) ? w0l : (w == 1) ? w1l : (w == 2) ? w2l : w3l;
    const int C = (w < 2) ? DD : KVD;
    const int R = DD;
    const int tx = tid & 31, ty = tid >> 5;            // 32 x 8
    int r0 = blockIdx.y * 32, c0 = blockIdx.x * 32;
    if (c0 >= C) return;
    __shared__ float t[32][33];
#pragma unroll
    for (int i = 0; i < 4; i++) {
        int r = r0 + ty + i * 8;
        t[ty + i * 8][tx] = in[(size_t)r * C + c0 + tx];
    }
    __syncthreads();
#pragma unroll
    for (int i = 0; i < 4; i++) {
        int c = c0 + ty + i * 8;
        float v = t[tx][ty + i * 8];
        bf16 h, l; split_bf16(v, h, l);
        hi[(size_t)c * R + r0 + tx] = h;
        lo[(size_t)c * R + r0 + tx] = l;
    }
}

// ============================================================================
// Tensor-core GEMM on pre-split bf16 (BM=BN=128, BK=32), multi-config:
// blockIdx.z selects one of three GemmCfg. Early-exit for narrow z-slices.
// Epilogue modes: 0 fp32 C, 1 split bf16 (with scale), 2 split bf16 V-T
// ============================================================================
#define BM 128
#define BN 128
#define BK 32
#define KSTR 40
#define TILE_BF (BM * KSTR)
#define STAGE_BF (4 * TILE_BF)
#define GEMM_SMEM (2 * STAGE_BF * 2)

struct GemmCfg {
    const bf16 *Ah, *Al, *Bh, *Bl;
    const float* bias;
    float* C;
    bf16 *Ch, *Cl;
    int   mode;
    float scale;
    int   N;
};

__device__ __forceinline__ void stage_tiles(
    bf16* base, const bf16* Ah, const bf16* Al, const bf16* Bh, const bf16* Bl,
    int row0, int col0, int kt, int K, int tid)
{
    bf16* pAh = base;               bf16* pAl = base + TILE_BF;
    bf16* pBh = base + 2 * TILE_BF; bf16* pBl = base + 3 * TILE_BF;
#pragma unroll
    for (int p = 0; p < 2; p++) {
        int c   = tid + p * 256;
        int r   = c >> 2;
        int off = (c & 3) * 8;
        const size_t ga = (size_t)(row0 + r) * K + kt + off;
        const size_t gb = (size_t)(col0 + r) * K + kt + off;
        const int so = r * KSTR + off;
        cpa16(pAh + so, Ah + ga);
        cpa16(pAl + so, Al + ga);
        cpa16(pBh + so, Bh + gb);
        cpa16(pBl + so, Bl + gb);
    }
}

__global__ __launch_bounds__(256, 2)
void gemm_tc(GemmCfg c0, GemmCfg c1, GemmCfg c2, int M, int K)
{
    const GemmCfg cf = (blockIdx.z == 0) ? c0 : (blockIdx.z == 1) ? c1 : c2;
    const int N = cf.N;
    if ((int)blockIdx.x * BN >= N) return;

    extern __shared__ bf16 smem[];

    const int tid  = threadIdx.x;
    const int lane = tid & 31;
    const int wid  = tid >> 5;
    const int wm   = wid & 1;
    const int wn   = wid >> 1;
    const int row0 = blockIdx.y * BM;
    const int col0 = blockIdx.x * BN;

    float acc[4][4][4];
#pragma unroll
    for (int i = 0; i < 4; i++)
#pragma unroll
        for (int j = 0; j < 4; j++)
#pragma unroll
            for (int k = 0; k < 4; k++) acc[i][j][k] = 0.f;

    const int a_r = lane & 15;
    const int a_k = (lane >> 4) << 3;
    const int b_r = (lane & 7) | ((lane & 16) >> 1);
    const int b_k = lane & 8;

    const int nt = K / BK;

    stage_tiles(smem, cf.Ah, cf.Al, cf.Bh, cf.Bl, row0, col0, 0, K, tid);
    asm volatile("cp.async.commit_group;");

    for (int t = 0; t < nt; t++) {
        if (t + 1 < nt)
            stage_tiles(smem + ((t + 1) & 1) * STAGE_BF,
                        cf.Ah, cf.Al, cf.Bh, cf.Bl, row0, col0, (t + 1) * BK, K, tid);
        asm volatile("cp.async.commit_group;");
        asm volatile("cp.async.wait_group 1;");
        __syncthreads();

        bf16* base = smem + (t & 1) * STAGE_BF;
        bf16* pAh = base;             bf16* pAl = base + TILE_BF;
        bf16* pBh = base + 2*TILE_BF; bf16* pBl = base + 3*TILE_BF;

#pragma unroll
        for (int kk = 0; kk < BK; kk += 16) {
            uint32_t af[4][4], bh[2][4], bl[2][4];
#pragma unroll
            for (int i = 0; i < 4; i++)
                ldmx4(af[i], pAh + (wm * 64 + i * 16 + a_r) * KSTR + kk + a_k);
#pragma unroll
            for (int j = 0; j < 2; j++)
                ldmx4(bh[j], pBh + (wn * 32 + j * 16 + b_r) * KSTR + kk + b_k);
#pragma unroll
            for (int j = 0; j < 2; j++)
                ldmx4(bl[j], pBl + (wn * 32 + j * 16 + b_r) * KSTR + kk + b_k);

#pragma unroll
            for (int i = 0; i < 4; i++)
#pragma unroll
                for (int j = 0; j < 4; j++)
                    mma16816(acc[i][j], af[i], &bh[j >> 1][(j & 1) * 2]);
#pragma unroll
            for (int i = 0; i < 4; i++)
#pragma unroll
                for (int j = 0; j < 4; j++)
                    mma16816(acc[i][j], af[i], &bl[j >> 1][(j & 1) * 2]);
#pragma unroll
            for (int i = 0; i < 4; i++)
                ldmx4(af[i], pAl + (wm * 64 + i * 16 + a_r) * KSTR + kk + a_k);
#pragma unroll
            for (int i = 0; i < 4; i++)
#pragma unroll
                for (int j = 0; j < 4; j++)
                    mma16816(acc[i][j], af[i], &bh[j >> 1][(j & 1) * 2]);
        }
        __syncthreads();
    }

    // epilogue
#pragma unroll
    for (int i = 0; i < 4; i++) {
        int gr = row0 + wm * 64 + i * 16 + (lane >> 2);
#pragma unroll
        for (int j = 0; j < 4; j++) {
            int gc = col0 + wn * 32 + j * 8 + (lane & 3) * 2;
            float bx = cf.bias[gc], by = cf.bias[gc + 1];
            float v0 = (acc[i][j][0] + bx) * cf.scale, v1 = (acc[i][j][1] + by) * cf.scale;
            float v2 = (acc[i][j][2] + bx) * cf.scale, v3 = (acc[i][j][3] + by) * cf.scale;
            if (cf.mode == 0) {
                *(float2*)&cf.C[(size_t)gr * N + gc]       = make_float2(v0, v1);
                *(float2*)&cf.C[(size_t)(gr + 8) * N + gc] = make_float2(v2, v3);
            } else if (cf.mode == 1) {
                uint32_t hp0, lp0, hp1, lp1;
                split2(v0, v1, hp0, lp0);
                split2(v2, v3, hp1, lp1);
                *(uint32_t*)&cf.Ch[(size_t)gr * N + gc]       = hp0;
                *(uint32_t*)&cf.Cl[(size_t)gr * N + gc]       = lp0;
                *(uint32_t*)&cf.Ch[(size_t)(gr + 8) * N + gc] = hp1;
                *(uint32_t*)&cf.Cl[(size_t)(gr + 8) * N + gc] = lp1;
            } else {
                int b0i = gr >> 10, s0 = gr & 1023;
                int b1i = (gr + 8) >> 10, s1 = (gr + 8) & 1023;
                bf16 h, l;
                size_t i00 = ((size_t)b0i * KVD + gc) * SS + s0;
                size_t i01 = ((size_t)b0i * KVD + gc + 1) * SS + s0;
                size_t i10 = ((size_t)b1i * KVD + gc) * SS + s1;
                size_t i11 = ((size_t)b1i * KVD + gc + 1) * SS + s1;
                split_bf16(v0, h, l); cf.Ch[i00] = h; cf.Cl[i00] = l;
                split_bf16(v1, h, l); cf.Ch[i01] = h; cf.Cl[i01] = l;
                split_bf16(v2, h, l); cf.Ch[i10] = h; cf.Cl[i10] = l;
                split_bf16(v3, h, l); cf.Ch[i11] = h; cf.Cl[i11] = l;
            }
        }
    }
}

// ============================================================================
// Tensor-core causal GQA flash attention (2 CTAs/SM, Q-lo persistent smem,
// double-buffered K/V, LPT y-order). Scores arrive in log2 domain
// (Q pre-scaled by 0.125*log2e) -> softmax uses bare ex2.
// ============================================================================
#define QSTR 72
#define QLO_ELEMS (128 * QSTR)
#define KVSTG (4 * 64 * QSTR)
#define ATTN_SMEM ((QLO_ELEMS + 2 * KVSTG) * 2)   // 92160 B

__global__ __launch_bounds__(256, 2)
void attn_mma(const bf16* __restrict__ Qh, const bf16* __restrict__ Ql,
              const bf16* __restrict__ Kh, const bf16* __restrict__ Kl,
              const bf16* __restrict__ Vth, const bf16* __restrict__ Vtl,
              bf16* __restrict__ Aoh, bf16* __restrict__ Aol)
{
    extern __shared__ bf16 sm[];
    bf16* sQl = sm;                          // persistent [128][QSTR]
    bf16* kvb = sm + QLO_ELEMS;              // 2 K/V stages

    const int tid = threadIdx.x, lane = tid & 31, wid = tid >> 5;
    const int y  = (gridDim.x - 1) - blockIdx.x;   // LPT: heavy tiles first
    const int bh = blockIdx.y;
    const int b  = bh >> 5, h = bh & 31, kh = h >> 2;
    const int qtok0 = b * SS + y * 128;

    const int a_r = lane & 15;
    const int a_k = (lane >> 4) << 3;
    const int b_r = (lane & 7) | ((lane & 16) >> 1);
    const int b_k = lane & 8;

    // ---- stage Q: hi transient (into KV stage-0 area), lo persistent ----
    bf16* sQh_t = kvb;
#pragma unroll
    for (int p = 0; p < 4; p++) {
        int c = tid + p * 256;
        int r = c >> 3, off = (c & 7) * 8;
        const size_t g = (size_t)(qtok0 + r) * DD + h * HD + off;
        cpa16(sQh_t + r * QSTR + off, Qh + g);
        cpa16(sQl   + r * QSTR + off, Ql + g);
    }
    asm volatile("cp.async.commit_group;");
    asm volatile("cp.async.wait_group 0;");
    __syncthreads();

    uint32_t qah[4][4];
#pragma unroll
    for (int kk = 0; kk < 4; kk++)
        ldmx4(qah[kk], sQh_t + (wid * 16 + a_r) * QSTR + kk * 16 + a_k);
    __syncthreads();

    float oacc[8][4];
#pragma unroll
    for (int f = 0; f < 8; f++)
#pragma unroll
        for (int e = 0; e < 4; e++) oacc[f][e] = 0.f;
    float mA = -1e30f, mB = -1e30f, lA = 0.f, lB = 0.f;

    const int qrowA = y * 128 + wid * 16 + (lane >> 2);
    const int jend = 2 * y + 1;

    auto stage_kv = [&](int s, int j) {
        bf16* base = kvb + s * KVSTG;
        bf16* pKh = base;
        bf16* pKl = base + 64 * QSTR;
        bf16* pVh = base + 128 * QSTR;
        bf16* pVl = base + 192 * QSTR;
        const int ktok0 = b * SS + j * 64;
#pragma unroll
        for (int p = 0; p < 2; p++) {
            int c = tid + p * 256;
            int r = c >> 3, off = (c & 7) * 8;
            const size_t gk = (size_t)(ktok0 + r) * KVD + kh * HD + off;
            cpa16(pKh + r * QSTR + off, Kh + gk);
            cpa16(pKl + r * QSTR + off, Kl + gk);
            const size_t gv = ((size_t)b * KVD + kh * HD + r) * SS + j * 64 + off;
            cpa16(pVh + r * QSTR + off, Vth + gv);
            cpa16(pVl + r * QSTR + off, Vtl + gv);
        }
    };

    stage_kv(0, 0);
    asm volatile("cp.async.commit_group;");

    for (int j = 0; j <= jend; j++) {
        if (j + 1 <= jend)
            stage_kv((j + 1) & 1, j + 1);
        asm volatile("cp.async.commit_group;");
        asm volatile("cp.async.wait_group 1;");
        __syncthreads();

        bf16* base = kvb + (j & 1) * KVSTG;
        bf16* sKh = base;
        bf16* sKl = base + 64 * QSTR;
        bf16* sVh = base + 128 * QSTR;
        bf16* sVl = base + 192 * QSTR;

        if (j * 64 <= y * 128 + wid * 16 + 15) {
            float sacc[8][4];
#pragma unroll
            for (int f = 0; f < 8; f++)
#pragma unroll
                for (int e = 0; e < 4; e++) sacc[f][e] = 0.f;

            uint32_t kb[4][4];
#pragma unroll
            for (int kk = 0; kk < 4; kk++) {
#pragma unroll
                for (int nb = 0; nb < 4; nb++)
                    ldmx4(kb[nb], sKh + (nb * 16 + b_r) * QSTR + kk * 16 + b_k);
#pragma unroll
                for (int f = 0; f < 8; f++)
                    mma16816(sacc[f], qah[kk], &kb[f >> 1][(f & 1) * 2]);
                uint32_t qalk[4];
                ldmx4(qalk, sQl + (wid * 16 + a_r) * QSTR + kk * 16 + a_k);
#pragma unroll
                for (int f = 0; f < 8; f++)
                    mma16816(sacc[f], qalk, &kb[f >> 1][(f & 1) * 2]);
#pragma unroll
                for (int nb = 0; nb < 4; nb++)
                    ldmx4(kb[nb], sKl + (nb * 16 + b_r) * QSTR + kk * 16 + b_k);
#pragma unroll
                for (int f = 0; f < 8; f++)
                    mma16816(sacc[f], qah[kk], &kb[f >> 1][(f & 1) * 2]);
            }

            if (j >= 2 * y) {
#pragma unroll
                for (int f = 0; f < 8; f++)
#pragma unroll
                    for (int e = 0; e < 4; e++) {
                        int kg = j * 64 + f * 8 + (lane & 3) * 2 + (e & 1);
                        int qg = qrowA + (e >> 1) * 8;
                        if (kg > qg) sacc[f][e] = -1e30f;
                    }
            }

            // ---- online softmax in log2 domain (scores = s * log2e) ----
            float tmA = -1e30f, tmB = -1e30f;
#pragma unroll
            for (int f = 0; f < 8; f++) {
                tmA = fmaxf(tmA, fmaxf(sacc[f][0], sacc[f][1]));
                tmB = fmaxf(tmB, fmaxf(sacc[f][2], sacc[f][3]));
            }
            tmA = fmaxf(tmA, __shfl_xor_sync(0xffffffffu, tmA, 1));
            tmA = fmaxf(tmA, __shfl_xor_sync(0xffffffffu, tmA, 2));
            tmB = fmaxf(tmB, __shfl_xor_sync(0xffffffffu, tmB, 1));
            tmB = fmaxf(tmB, __shfl_xor_sync(0xffffffffu, tmB, 2));
            float mnA = fmaxf(mA, tmA), mnB = fmaxf(mB, tmB);
            float alA = ex2(mA - mnA), alB = ex2(mB - mnB);
            mA = mnA; mB = mnB;

            float suA = 0.f, suB = 0.f;
#pragma unroll
            for (int f = 0; f < 8; f++) {
                float p0 = ex2(sacc[f][0] - mA);
                float p1 = ex2(sacc[f][1] - mA);
                float p2 = ex2(sacc[f][2] - mB);
                float p3 = ex2(sacc[f][3] - mB);
                suA += p0 + p1; suB += p2 + p3;
                sacc[f][0] = p0; sacc[f][1] = p1; sacc[f][2] = p2; sacc[f][3] = p3;
            }
            suA += __shfl_xor_sync(0xffffffffu, suA, 1);
            suA += __shfl_xor_sync(0xffffffffu, suA, 2);
            suB += __shfl_xor_sync(0xffffffffu, suB, 1);
            suB += __shfl_xor_sync(0xffffffffu, suB, 2);
            lA = lA * alA + suA; lB = lB * alB + suB;

#pragma unroll
            for (int f = 0; f < 8; f++) {
                oacc[f][0] *= alA; oacc[f][1] *= alA;
                oacc[f][2] *= alB; oacc[f][3] *= alB;
            }

            uint32_t vb[4][4];
#pragma unroll
            for (int c = 0; c < 4; c++) {
                const int f0 = 2 * c, f1 = 2 * c + 1;
                uint32_t pah[4], pal[4];
                split2(sacc[f0][0], sacc[f0][1], pah[0], pal[0]);
                split2(sacc[f0][2], sacc[f0][3], pah[1], pal[1]);
                split2(sacc[f1][0], sacc[f1][1], pah[2], pal[2]);
                split2(sacc[f1][2], sacc[f1][3], pah[3], pal[3]);
#pragma unroll
                for (int nb = 0; nb < 4; nb++)
                    ldmx4(vb[nb], sVh + (nb * 16 + b_r) * QSTR + c * 16 + b_k);
#pragma unroll
                for (int f = 0; f < 8; f++)
                    mma16816(oacc[f], pah, &vb[f >> 1][(f & 1) * 2]);
#pragma unroll
                for (int f = 0; f < 8; f++)
                    mma16816(oacc[f], pal, &vb[f >> 1][(f & 1) * 2]);
#pragma unroll
                for (int nb = 0; nb < 4; nb++)
                    ldmx4(vb[nb], sVl + (nb * 16 + b_r) * QSTR + c * 16 + b_k);
#pragma unroll
                for (int f = 0; f < 8; f++)
                    mma16816(oacc[f], pah, &vb[f >> 1][(f & 1) * 2]);
            }
        }
        __syncthreads();
    }

    const float ivA = 1.f / lA, ivB = 1.f / lB;
    const int tokA = qtok0 + wid * 16 + (lane >> 2);
#pragma unroll
    for (int f = 0; f < 8; f++) {
        int col = h * HD + f * 8 + (lane & 3) * 2;
        uint32_t hpA, lpA, hpB, lpB;
        split2(oacc[f][0] * ivA, oacc[f][1] * ivA, hpA, lpA);
        split2(oacc[f][2] * ivB, oacc[f][3] * ivB, hpB, lpB);
        *(uint32_t*)&Aoh[(size_t)tokA * DD + col]       = hpA;
        *(uint32_t*)&Aol[(size_t)tokA * DD + col]       = lpA;
        *(uint32_t*)&Aoh[(size_t)(tokA + 8) * DD + col] = hpB;
        *(uint32_t*)&Aol[(size_t)(tokA + 8) * DD + col] = lpB;
    }
}

// ---------------- launcher ----------------
extern "C" void kernel_launch(void* const* d_in, const int* in_sizes, int n_in,
                              void* d_out, int out_size)
{
    const float* q  = (const float*)d_in[0];
    const float* kv = (const float*)d_in[1];
    // d_in[2] = mask (causal, static) -- unused
    const float* Wq = (const float*)d_in[3];
    const float* bq = (const float*)d_in[4];
    const float* Wk = (const float*)d_in[5];
    const float* bk = (const float*)d_in[6];
    const float* Wv = (const float*)d_in[7];
    const float* bv = (const float*)d_in[8];
    const float* Wo = (const float*)d_in[9];
    const float* bo = (const float*)d_in[10];
    float* out = (float*)d_out;

    bf16 *qh, *ql, *kvh, *kvl, *Wqth, *Wqtl, *Wkth, *Wktl, *Wvth_, *Wvtl_, *Woth, *Wotl;
    bf16 *Qsh, *Qsl, *Ksh, *Ksl, *Vth, *Vtl, *Aoh, *Aol;
    cudaGetSymbolAddress((void**)&qh,  g_qh);   cudaGetSymbolAddress((void**)&ql,  g_ql);
    cudaGetSymbolAddress((void**)&kvh, g_kvh);  cudaGetSymbolAddress((void**)&kvl, g_kvl);
    cudaGetSymbolAddress((void**)&Wqth, g_Wqt_h); cudaGetSymbolAddress((void**)&Wqtl, g_Wqt_l);
    cudaGetSymbolAddress((void**)&Wkth, g_Wkt_h); cudaGetSymbolAddress((void**)&Wktl, g_Wkt_l);
    cudaGetSymbolAddress((void**)&Wvth_, g_Wvt_h); cudaGetSymbolAddress((void**)&Wvtl_, g_Wvt_l);
    cudaGetSymbolAddress((void**)&Woth, g_Wot_h); cudaGetSymbolAddress((void**)&Wotl, g_Wot_l);
    cudaGetSymbolAddress((void**)&Qsh, g_Qsh);  cudaGetSymbolAddress((void**)&Qsl, g_Qsl);
    cudaGetSymbolAddress((void**)&Ksh, g_Ksh);  cudaGetSymbolAddress((void**)&Ksl, g_Ksl);
    cudaGetSymbolAddress((void**)&Vth, g_Vth);  cudaGetSymbolAddress((void**)&Vtl, g_Vtl);
    cudaGetSymbolAddress((void**)&Aoh, g_Aoh);  cudaGetSymbolAddress((void**)&Aol, g_Aol);

    cudaFuncSetAttribute(gemm_tc,
                         cudaFuncAttributeMaxDynamicSharedMemorySize, GEMM_SMEM);
    cudaFuncSetAttribute(attn_mma,
                         cudaFuncAttributeMaxDynamicSharedMemorySize, ATTN_SMEM);

    // ---- all converts in ONE launch ----
    k_conv<<<dim3(64, 64, 6), 256>>>(
        q, qh, ql, kv, kvh, kvl,
        Wq, Wqth, Wqtl, Wo, Woth, Wotl, Wk, Wkth, Wktl, Wv, Wvth_, Wvtl_);

    // ---- Q + K + V projections fused (Q pre-scaled by 0.125*log2e) ----
    GemmCfg cq { qh,  ql,  Wqth,  Wqtl,  bq, nullptr, Qsh, Qsl, 1,
                 0.125f * 1.44269504088896341f, DD };
    GemmCfg ck { kvh, kvl, Wkth,  Wktl,  bk, nullptr, Ksh, Ksl, 1, 1.0f, KVD };
    GemmCfg cv { kvh, kvl, Wvth_, Wvtl_, bv, nullptr, Vth, Vtl, 2, 1.0f, KVD };
    gemm_tc<<<dim3(DD / BN, MTOT / BM, 3), 256, GEMM_SMEM>>>(cq, ck, cv, MTOT, DD);

    // ---- tensor-core attention -> Ao split ----
    attn_mma<<<dim3(SS / 128, BB * QH), 256, ATTN_SMEM>>>(
        Qsh, Qsl, Ksh, Ksl, Vth, Vtl, Aoh, Aol);

    // ---- output projection (fp32 out) ----
    GemmCfg co { Aoh, Aol, Woth, Wotl, bo, out, nullptr, nullptr, 0, 1.0f, DD };
    gemm_tc<<<dim3(DD / BN, MTOT / BM, 1), 256, GEMM_SMEM>>>(co, co, co, MTOT, DD);
}